// round 6
// baseline (speedup 1.0000x reference)
#include <cuda_runtime.h>
#include <cstdint>

#define B_    64
#define S_    1024
#define CIN   5
#define KS    4
#define H1    64
#define H2    16
#define OUTC  32
#define L1    1021
#define C1    22
#define SIGC1 506
#define SC1P  512
#define L2    1018
#define SIGC2 272
#define NC1   16
#define CH1   64

// conv2 tiling
#define TM    128
#define SAS   130
#define SZ    66
#define SW    68
#define GEMMF (64*SAS + 64*128)          // 8320 + 8192 = 16512 floats
#define EPIF  (128*SZ + 64*SW)           // 12800 floats
#define DSMF  (GEMMF > EPIF ? GEMMF : EPIF)
#define DSMB  (DSMF * 4)                 // 66048 bytes

// ---- scratch ----
__device__ float g_h[B_ * L1 * C1];
__device__ float g_s1[(size_t)B_ * L1 * SC1P];
__device__ float g_wdup[KS * SC1P * 128];
__device__ float g_csum[B_ * NC1 * SC1P];
__device__ float g_h2[B_ * L2 * H2];

__device__ __forceinline__ unsigned long long ffma2(
    unsigned long long a, unsigned long long b, unsigned long long c) {
    unsigned long long d;
    asm("fma.rn.f32x2 %0, %1, %2, %3;" : "=l"(d) : "l"(a), "l"(b), "l"(c));
    return d;
}
__device__ __forceinline__ void unpack2(unsigned long long p, float& lo, float& hi) {
    unsigned int a, b;
    asm("mov.b64 {%0, %1}, %2;" : "=r"(a), "=r"(b) : "l"(p));
    lo = __uint_as_float(a); hi = __uint_as_float(b);
}

// ============================================================
// Repack a2_w0 (O,C,K) -> wdup[k][c_pad][2o]=[2o+1]=w
// ============================================================
__global__ void k_repack(const float* __restrict__ w0) {
    int idx = blockIdx.x * blockDim.x + threadIdx.x;   // 0..262143
    int o  = (idx >> 1) & 63;
    int c  = (idx >> 7) & (SC1P - 1);
    int kk = idx >> 16;
    float v = 0.f;
    if (c < SIGC1) v = w0[(o * SIGC1 + c) * KS + kk];
    g_wdup[idx] = v;
}

// ============================================================
// Augment 1
// ============================================================
__global__ __launch_bounds__(128) void k_aug1(
    const float* __restrict__ x,
    const float* __restrict__ w0, const float* __restrict__ b0,
    const float* __restrict__ w1, const float* __restrict__ b1,
    const float* __restrict__ w2, const float* __restrict__ b2)
{
    __shared__ float w0s[H1*CIN*KS], w1s[H1*H1], w2s[H2*H1];
    __shared__ float b0s[H1], b1s[H1], b2s[H2];
    int tid = threadIdx.x;
    for (int i = tid; i < H1*CIN*KS; i += 128) w0s[i] = w0[i];
    for (int i = tid; i < H1*H1;     i += 128) w1s[i] = w1[i];
    for (int i = tid; i < H2*H1;     i += 128) w2s[i] = w2[i];
    if (tid < H1) { b0s[tid] = b0[tid]; b1s[tid] = b1[tid]; }
    if (tid < H2) b2s[tid] = b2[tid];
    __syncthreads();

    int b = blockIdx.y;
    int t = blockIdx.x * 128 + tid;
    if (t >= L1) return;

    float xr[KS][CIN];
#pragma unroll
    for (int k = 0; k < KS; k++)
#pragma unroll
        for (int c = 0; c < CIN; c++)
            xr[k][c] = x[((size_t)(b * S_) + t + k) * CIN + c];

    float z1[H1];
#pragma unroll
    for (int o = 0; o < H1; o++) {
        float s = b0s[o];
#pragma unroll
        for (int c = 0; c < CIN; c++)
#pragma unroll
            for (int k = 0; k < KS; k++)
                s += w0s[(o*CIN + c)*KS + k] * xr[k][c];
        z1[o] = fmaxf(s, 0.f);
    }
    float z3[H2];
#pragma unroll
    for (int o = 0; o < H2; o++) z3[o] = b2s[o];
    for (int o2 = 0; o2 < H1; o2++) {
        float s = b1s[o2];
#pragma unroll
        for (int c = 0; c < H1; c++) s += w1s[o2*H1 + c] * z1[c];
        s = fmaxf(s, 0.f);
#pragma unroll
        for (int o = 0; o < H2; o++) z3[o] += w2s[o*H1 + o2] * s;
    }
    float* hrow = &g_h[(size_t)(b * L1 + t) * C1];
#pragma unroll
    for (int c = 0; c < CIN; c++) hrow[c] = xr[KS-1][c];
    hrow[CIN] = (float)t * (1.0f / (float)(L1 - 1));
#pragma unroll
    for (int o = 0; o < H2; o++) hrow[CIN + 1 + o] = z3[o];
}

// ============================================================
// Sig1 passes
// ============================================================
__global__ __launch_bounds__(512) void k_sig1_sum() {
    __shared__ float hs[CH1 + 1][C1];
    int b = blockIdx.y, nc = blockIdx.x, tid = threadIdx.x;
    int c0 = nc * CH1;
    for (int idx = tid; idx < (CH1 + 1) * C1; idx += 512) {
        int r = idx / C1, c = idx - r * C1;
        int row = c0 - 1 + r;
        hs[r][c] = (row >= 0 && row < L1) ? g_h[(size_t)(b * L1 + row) * C1 + c] : 0.f;
    }
    __syncthreads();
    if (tid >= C1 * C1) return;
    int i = tid / C1, j = tid - i * C1;
    float acc = 0.f;
    int tend = min(c0 + CH1, L1);
    for (int t = c0; t < tend; t++) {
        int r = t - c0 + 1;
        float hpi = hs[r-1][i], hpj = hs[r-1][j];
        float dxi = hs[r][i] - hpi, dxj = hs[r][j] - hpj;
        acc += hpi * dxj + 0.5f * dxi * dxj;
    }
    g_csum[(b * NC1 + nc) * SC1P + tid] = acc;
}

__global__ void k_sig1_prefix() {
    int b = blockIdx.x, tid = threadIdx.x;
    if (tid >= C1 * C1) return;
    float run = 0.f;
    for (int nc = 0; nc < NC1; nc++) {
        int idx = (b * NC1 + nc) * SC1P + tid;
        float v = g_csum[idx];
        g_csum[idx] = run;
        run += v;
    }
}

__global__ __launch_bounds__(512) void k_sig1_write() {
    __shared__ float hs[CH1 + 1][C1];
    int b = blockIdx.y, nc = blockIdx.x, tid = threadIdx.x;
    int c0 = nc * CH1;
    for (int idx = tid; idx < (CH1 + 1) * C1; idx += 512) {
        int r = idx / C1, c = idx - r * C1;
        int row = c0 - 1 + r;
        hs[r][c] = (row >= 0 && row < L1) ? g_h[(size_t)(b * L1 + row) * C1 + c] : 0.f;
    }
    __syncthreads();
    int tend = min(c0 + CH1, L1);
    if (tid < C1 * C1) {
        int i = tid / C1, j = tid - i * C1;
        float acc = g_csum[(b * NC1 + nc) * SC1P + tid];
        for (int t = c0; t < tend; t++) {
            int r = t - c0 + 1;
            float hpi = hs[r-1][i], hpj = hs[r-1][j];
            float dxi = hs[r][i] - hpi, dxj = hs[r][j] - hpj;
            acc += hpi * dxj + 0.5f * dxi * dxj;
            g_s1[((size_t)(b * L1 + t)) * SC1P + C1 + tid] = acc;
        }
    } else {
        int c = tid - C1 * C1;
        int ch = (c < C1) ? c : (C1 * C1 + c);
        for (int t = c0; t < tend; t++) {
            int r = t - c0 + 1;
            float v = (c < C1) ? hs[r][c] : 0.f;
            g_s1[((size_t)(b * L1 + t)) * SC1P + ch] = v;
        }
    }
}

// ============================================================
// Conv stack 2: 128x64 GEMM (K=2048), FFMA2, KC=64, dup-W smem
// ============================================================
__global__ __launch_bounds__(256, 3) void k_conv2(
    const float* __restrict__ b0,
    const float* __restrict__ w1, const float* __restrict__ b1,
    const float* __restrict__ w2, const float* __restrict__ b2)
{
    extern __shared__ float dsm[];
    float* As = dsm;               // [64][SAS]  c-major, m contiguous
    float* Bs = dsm + 64 * SAS;    // [64][128]  duplicated pairs
    float* Z  = dsm;               // [128][SZ]
    float* Wm = dsm + 128 * SZ;    // [64][SW]
    __shared__ float b0s[64], b1s[64], b2s[16];

    int tid = threadIdx.x;
    int b = blockIdx.y, t0 = blockIdx.x * TM;
    if (tid < 64) { b0s[tid] = b0[tid]; b1s[tid] = b1[tid]; }
    if (tid < 16) b2s[tid] = b2[tid];

    int tx = tid & 15, ty = tid >> 4;
    int m0 = ty * 8, n0 = tx * 4;

    unsigned long long acc2[4][4];
#pragma unroll
    for (int p = 0; p < 4; p++)
#pragma unroll
        for (int j = 0; j < 4; j++) acc2[p][j] = 0ULL;

    const float* pAbase = g_s1 + (size_t)b * L1 * SC1P;
    int ac4 = tid & 15;
    for (int kb = 0; kb < 32; kb++) {
        int kk = kb >> 3;
        int cb = (kb & 7) << 6;
        // A tile: 128 rows x 64 ch -> As[c][m]
#pragma unroll
        for (int q = 0; q < 8; q++) {
            int idx = tid + q * 256;
            int m = idx >> 4;
            int row = t0 + kk + m;
            float4 v = make_float4(0.f, 0.f, 0.f, 0.f);
            if (row < L1)
                v = *(const float4*)&pAbase[(size_t)row * SC1P + cb + ac4 * 4];
            As[(ac4*4+0)*SAS + m] = v.x;
            As[(ac4*4+1)*SAS + m] = v.y;
            As[(ac4*4+2)*SAS + m] = v.z;
            As[(ac4*4+3)*SAS + m] = v.w;
        }
        const float4* pB = (const float4*)(g_wdup + (kk * SC1P + cb) * 128);
#pragma unroll
        for (int q = 0; q < 8; q++)
            ((float4*)Bs)[tid + q * 256] = pB[tid + q * 256];
        __syncthreads();
#pragma unroll
        for (int k = 0; k < 64; k++) {
            const ulonglong2* pw = (const ulonglong2*)&Bs[k * 128 + 2 * n0];
            ulonglong2 w01 = pw[0], w23 = pw[1];
            unsigned long long wp0 = w01.x, wp1 = w01.y, wp2 = w23.x, wp3 = w23.y;
            const unsigned long long* pa = (const unsigned long long*)&As[k * SAS + m0];
            unsigned long long a0 = pa[0], a1 = pa[1], a2v = pa[2], a3 = pa[3];
            acc2[0][0] = ffma2(a0, wp0, acc2[0][0]);
            acc2[0][1] = ffma2(a0, wp1, acc2[0][1]);
            acc2[0][2] = ffma2(a0, wp2, acc2[0][2]);
            acc2[0][3] = ffma2(a0, wp3, acc2[0][3]);
            acc2[1][0] = ffma2(a1, wp0, acc2[1][0]);
            acc2[1][1] = ffma2(a1, wp1, acc2[1][1]);
            acc2[1][2] = ffma2(a1, wp2, acc2[1][2]);
            acc2[1][3] = ffma2(a1, wp3, acc2[1][3]);
            acc2[2][0] = ffma2(a2v, wp0, acc2[2][0]);
            acc2[2][1] = ffma2(a2v, wp1, acc2[2][1]);
            acc2[2][2] = ffma2(a2v, wp2, acc2[2][2]);
            acc2[2][3] = ffma2(a2v, wp3, acc2[2][3]);
            acc2[3][0] = ffma2(a3, wp0, acc2[3][0]);
            acc2[3][1] = ffma2(a3, wp1, acc2[3][1]);
            acc2[3][2] = ffma2(a3, wp2, acc2[3][2]);
            acc2[3][3] = ffma2(a3, wp3, acc2[3][3]);
        }
        __syncthreads();
    }

    // ---- epilogue ----
#pragma unroll
    for (int p = 0; p < 4; p++)
#pragma unroll
        for (int j = 0; j < 4; j++) {
            float lo, hi;
            unpack2(acc2[p][j], lo, hi);
            Z[(m0 + 2*p    ) * SZ + n0 + j] = fmaxf(lo + b0s[n0 + j], 0.f);
            Z[(m0 + 2*p + 1) * SZ + n0 + j] = fmaxf(hi + b0s[n0 + j], 0.f);
        }
#pragma unroll
    for (int q = 0; q < 16; q++) {
        int idx = tid + q * 256;
        Wm[(idx & 63) * SW + (idx >> 6)] = w1[idx];
    }
    __syncthreads();

    float a2[8][4];
#pragma unroll
    for (int i = 0; i < 8; i++)
#pragma unroll
        for (int j = 0; j < 4; j++) a2[i][j] = b1s[n0 + j];
#pragma unroll 4
    for (int c = 0; c < 64; c++) {
        float4 wv = *(const float4*)&Wm[c * SW + n0];
#pragma unroll
        for (int i = 0; i < 8; i++) {
            float zi = Z[(m0 + i) * SZ + c];
            a2[i][0] += zi * wv.x; a2[i][1] += zi * wv.y;
            a2[i][2] += zi * wv.z; a2[i][3] += zi * wv.w;
        }
    }
    __syncthreads();
#pragma unroll
    for (int i = 0; i < 8; i++)
#pragma unroll
        for (int j = 0; j < 4; j++)
            Z[(m0 + i) * SZ + n0 + j] = fmaxf(a2[i][j], 0.f);
#pragma unroll
    for (int q = 0; q < 4; q++) {
        int idx = tid + q * 256;
        Wm[(idx >> 6) * SW + (idx & 63)] = w2[idx];
    }
    __syncthreads();
    int o3 = tid & 15;
    int mb = tid >> 4;
#pragma unroll
    for (int g2 = 0; g2 < 8; g2++) {
        int m = mb + g2 * 16;
        float s = b2s[o3];
#pragma unroll 16
        for (int c = 0; c < 64; c++) s += Wm[o3 * SW + c] * Z[m * SZ + c];
        int t = t0 + m;
        if (t < L2) g_h2[(size_t)(b * L2 + t) * H2 + o3] = s;
    }
}

// ============================================================
// become_constant + sig2 + linear
// ============================================================
__global__ __launch_bounds__(256) void k_sig2(
    const int* __restrict__ lengths,
    const float* __restrict__ lw, const float* __restrict__ lb,
    float* __restrict__ out)
{
    __shared__ float hs[129][16];
    __shared__ float s2s[SIGC2];
    int b = blockIdx.x, tid = threadIdx.x;
    int adj = lengths[b] - 2 * KS + 2;
    if (adj < 1) adj = 1;
    if (adj > L2) adj = L2;
    int i = tid >> 4, j = tid & 15;
    float acc = 0.f;
    for (int c0 = 0; c0 < adj; c0 += 128) {
        for (int idx = tid; idx < 129 * 16; idx += 256) {
            int r = idx >> 4, c = idx & 15;
            int row = c0 - 1 + r;
            hs[r][c] = (row >= 0 && row < L2) ? g_h2[(size_t)(b * L2 + row) * H2 + c] : 0.f;
        }
        __syncthreads();
        int tend = min(c0 + 128, adj);
        for (int t = c0; t < tend; t++) {
            int r = t - c0 + 1;
            float hpi = hs[r-1][i], hpj = hs[r-1][j];
            float dxi = hs[r][i] - hpi, dxj = hs[r][j] - hpj;
            acc += hpi * dxj + 0.5f * dxi * dxj;
        }
        __syncthreads();
    }
    s2s[16 + tid] = acc;
    if (tid < 16) s2s[tid] = g_h2[(size_t)(b * L2 + adj - 1) * H2 + tid];
    __syncthreads();
    if (tid < OUTC) {
        float v = lb[tid];
        for (int c = 0; c < SIGC2; c++) v += lw[tid * SIGC2 + c] * s2s[c];
        out[b * OUTC + tid] = v;
    }
}

// ============================================================
extern "C" void kernel_launch(void* const* d_in, const int* in_sizes, int n_in,
                              void* d_out, int out_size) {
    const float* x      = (const float*)d_in[0];
    const int*   lens   = (const int*)  d_in[1];
    const float* a1_w0  = (const float*)d_in[2];
    const float* a1_b0  = (const float*)d_in[3];
    const float* a1_w1  = (const float*)d_in[4];
    const float* a1_b1  = (const float*)d_in[5];
    const float* a1_w2  = (const float*)d_in[6];
    const float* a1_b2  = (const float*)d_in[7];
    const float* a2_w0  = (const float*)d_in[8];
    const float* a2_b0  = (const float*)d_in[9];
    const float* a2_w1  = (const float*)d_in[10];
    const float* a2_b1  = (const float*)d_in[11];
    const float* a2_w2  = (const float*)d_in[12];
    const float* a2_b2  = (const float*)d_in[13];
    const float* lin_w  = (const float*)d_in[14];
    const float* lin_b  = (const float*)d_in[15];
    float* out = (float*)d_out;

    static bool attr_set = false;
    if (!attr_set) {
        cudaFuncSetAttribute(k_conv2, cudaFuncAttributeMaxDynamicSharedMemorySize, DSMB);
        attr_set = true;
    }

    k_repack<<<1024, 256>>>(a2_w0);
    k_aug1<<<dim3(8, B_), 128>>>(x, a1_w0, a1_b0, a1_w1, a1_b1, a1_w2, a1_b2);
    k_sig1_sum<<<dim3(NC1, B_), 512>>>();
    k_sig1_prefix<<<B_, 512>>>();
    k_sig1_write<<<dim3(NC1, B_), 512>>>();
    k_conv2<<<dim3(8, B_), 256, DSMB>>>(a2_b0, a2_w1, a2_b1, a2_w2, a2_b2);
    k_sig2<<<B_, 256>>>(lens, lin_w, lin_b, out);
}

// round 7
// speedup vs baseline: 1.6991x; 1.6991x over previous
#include <cuda_runtime.h>
#include <cstdint>

#define B_    64
#define S_    1024
#define CIN   5
#define KS    4
#define H1    64
#define H2    16
#define OUTC  32
#define L1    1021
#define C1    22
#define SIGC1 506
#define SC1P  512
#define L2    1018
#define SIGC2 272
#define NC1   16
#define CH1   64

// conv2 tiling: M-tile 256, micro 16m x 4n
#define TM    256
#define SAS   258           // As row stride (floats), 8B-aligned
#define SZ    66
#define SW    68
#define GEMMF (64*SAS + 64*64)           // 16512 + 4096 = 20608
#define EPIF  (256*SZ + 64*SW)           // 16896 + 4352 = 21248
#define DSMF  (GEMMF > EPIF ? GEMMF : EPIF)
#define DSMB  (DSMF * 4)                 // 84992 bytes

// ---- scratch ----
__device__ float g_h[B_ * L1 * C1];
__device__ float g_s1[(size_t)B_ * L1 * SC1P];
__device__ float g_wpad[KS * SC1P * H1];
__device__ float g_csum[B_ * NC1 * SC1P];
__device__ float g_h2[B_ * L2 * H2];

__device__ __forceinline__ unsigned long long ffma2(
    unsigned long long a, unsigned long long b, unsigned long long c) {
    unsigned long long d;
    asm("fma.rn.f32x2 %0, %1, %2, %3;" : "=l"(d) : "l"(a), "l"(b), "l"(c));
    return d;
}
__device__ __forceinline__ unsigned long long pack2(float v) {
    unsigned long long d;
    unsigned int r = __float_as_uint(v);
    asm("mov.b64 %0, {%1, %1};" : "=l"(d) : "r"(r));
    return d;
}
__device__ __forceinline__ void unpack2(unsigned long long p, float& lo, float& hi) {
    unsigned int a, b;
    asm("mov.b64 {%0, %1}, %2;" : "=r"(a), "=r"(b) : "l"(p));
    lo = __uint_as_float(a); hi = __uint_as_float(b);
}

// ============================================================
// Repack a2_w0 (O,C,K) -> wpad[k][c_pad][o]
// ============================================================
__global__ void k_repack(const float* __restrict__ w0) {
    int idx = blockIdx.x * blockDim.x + threadIdx.x;
    int o  = idx & 63;
    int c  = (idx >> 6) & (SC1P - 1);
    int kk = idx >> 15;
    float v = 0.f;
    if (c < SIGC1) v = w0[(o * SIGC1 + c) * KS + kk];
    g_wpad[idx] = v;
}

// ============================================================
// Augment 1
// ============================================================
__global__ __launch_bounds__(128) void k_aug1(
    const float* __restrict__ x,
    const float* __restrict__ w0, const float* __restrict__ b0,
    const float* __restrict__ w1, const float* __restrict__ b1,
    const float* __restrict__ w2, const float* __restrict__ b2)
{
    __shared__ float w0s[H1*CIN*KS], w1s[H1*H1], w2s[H2*H1];
    __shared__ float b0s[H1], b1s[H1], b2s[H2];
    int tid = threadIdx.x;
    for (int i = tid; i < H1*CIN*KS; i += 128) w0s[i] = w0[i];
    for (int i = tid; i < H1*H1;     i += 128) w1s[i] = w1[i];
    for (int i = tid; i < H2*H1;     i += 128) w2s[i] = w2[i];
    if (tid < H1) { b0s[tid] = b0[tid]; b1s[tid] = b1[tid]; }
    if (tid < H2) b2s[tid] = b2[tid];
    __syncthreads();

    int b = blockIdx.y;
    int t = blockIdx.x * 128 + tid;
    if (t >= L1) return;

    float xr[KS][CIN];
#pragma unroll
    for (int k = 0; k < KS; k++)
#pragma unroll
        for (int c = 0; c < CIN; c++)
            xr[k][c] = x[((size_t)(b * S_) + t + k) * CIN + c];

    float z1[H1];
#pragma unroll
    for (int o = 0; o < H1; o++) {
        float s = b0s[o];
#pragma unroll
        for (int c = 0; c < CIN; c++)
#pragma unroll
            for (int k = 0; k < KS; k++)
                s += w0s[(o*CIN + c)*KS + k] * xr[k][c];
        z1[o] = fmaxf(s, 0.f);
    }
    float z3[H2];
#pragma unroll
    for (int o = 0; o < H2; o++) z3[o] = b2s[o];
    for (int o2 = 0; o2 < H1; o2++) {
        float s = b1s[o2];
#pragma unroll
        for (int c = 0; c < H1; c++) s += w1s[o2*H1 + c] * z1[c];
        s = fmaxf(s, 0.f);
#pragma unroll
        for (int o = 0; o < H2; o++) z3[o] += w2s[o*H1 + o2] * s;
    }
    float* hrow = &g_h[(size_t)(b * L1 + t) * C1];
#pragma unroll
    for (int c = 0; c < CIN; c++) hrow[c] = xr[KS-1][c];
    hrow[CIN] = (float)t * (1.0f / (float)(L1 - 1));
#pragma unroll
    for (int o = 0; o < H2; o++) hrow[CIN + 1 + o] = z3[o];
}

// ============================================================
// Sig1 passes
// ============================================================
__global__ __launch_bounds__(512) void k_sig1_sum() {
    __shared__ float hs[CH1 + 1][C1];
    int b = blockIdx.y, nc = blockIdx.x, tid = threadIdx.x;
    int c0 = nc * CH1;
    for (int idx = tid; idx < (CH1 + 1) * C1; idx += 512) {
        int r = idx / C1, c = idx - r * C1;
        int row = c0 - 1 + r;
        hs[r][c] = (row >= 0 && row < L1) ? g_h[(size_t)(b * L1 + row) * C1 + c] : 0.f;
    }
    __syncthreads();
    if (tid >= C1 * C1) return;
    int i = tid / C1, j = tid - i * C1;
    float acc = 0.f;
    int tend = min(c0 + CH1, L1);
    for (int t = c0; t < tend; t++) {
        int r = t - c0 + 1;
        float hpi = hs[r-1][i], hpj = hs[r-1][j];
        float dxi = hs[r][i] - hpi, dxj = hs[r][j] - hpj;
        acc += hpi * dxj + 0.5f * dxi * dxj;
    }
    g_csum[(b * NC1 + nc) * SC1P + tid] = acc;
}

__global__ void k_sig1_prefix() {
    int b = blockIdx.x, tid = threadIdx.x;
    if (tid >= C1 * C1) return;
    float run = 0.f;
    for (int nc = 0; nc < NC1; nc++) {
        int idx = (b * NC1 + nc) * SC1P + tid;
        float v = g_csum[idx];
        g_csum[idx] = run;
        run += v;
    }
}

__global__ __launch_bounds__(512) void k_sig1_write() {
    __shared__ float hs[CH1 + 1][C1];
    int b = blockIdx.y, nc = blockIdx.x, tid = threadIdx.x;
    int c0 = nc * CH1;
    for (int idx = tid; idx < (CH1 + 1) * C1; idx += 512) {
        int r = idx / C1, c = idx - r * C1;
        int row = c0 - 1 + r;
        hs[r][c] = (row >= 0 && row < L1) ? g_h[(size_t)(b * L1 + row) * C1 + c] : 0.f;
    }
    __syncthreads();
    int tend = min(c0 + CH1, L1);
    if (tid < C1 * C1) {
        int i = tid / C1, j = tid - i * C1;
        float acc = g_csum[(b * NC1 + nc) * SC1P + tid];
        for (int t = c0; t < tend; t++) {
            int r = t - c0 + 1;
            float hpi = hs[r-1][i], hpj = hs[r-1][j];
            float dxi = hs[r][i] - hpi, dxj = hs[r][j] - hpj;
            acc += hpi * dxj + 0.5f * dxi * dxj;
            g_s1[((size_t)(b * L1 + t)) * SC1P + C1 + tid] = acc;
        }
    } else {
        int c = tid - C1 * C1;
        int ch = (c < C1) ? c : (C1 * C1 + c);
        for (int t = c0; t < tend; t++) {
            int r = t - c0 + 1;
            float v = (c < C1) ? hs[r][c] : 0.f;
            g_s1[((size_t)(b * L1 + t)) * SC1P + ch] = v;
        }
    }
}

// ============================================================
// Conv stack 2: 256x64 tile GEMM (K=2048), FFMA2, micro 16m x 4n
// ============================================================
__global__ __launch_bounds__(256, 2) void k_conv2(
    const float* __restrict__ b0,
    const float* __restrict__ w1, const float* __restrict__ b1,
    const float* __restrict__ w2, const float* __restrict__ b2)
{
    extern __shared__ float dsm[];
    float* As = dsm;               // [64][SAS]  c-major, m contiguous (256 m)
    float* Bs = dsm + 64 * SAS;    // [64][64]
    float* Z  = dsm;               // [256][SZ]
    float* Wm = dsm + 256 * SZ;    // [64][SW]
    __shared__ float b0s[64], b1s[64], b2s[16];

    int tid = threadIdx.x;
    int b = blockIdx.y, t0 = blockIdx.x * TM;
    if (tid < 64) { b0s[tid] = b0[tid]; b1s[tid] = b1[tid]; }
    if (tid < 16) b2s[tid] = b2[tid];

    int tx = tid & 15, ty = tid >> 4;
    int m0 = ty * 16, n0 = tx * 4;

    unsigned long long acc2[8][4];
#pragma unroll
    for (int p = 0; p < 8; p++)
#pragma unroll
        for (int j = 0; j < 4; j++) acc2[p][j] = 0ULL;

    const float* pAbase = g_s1 + (size_t)b * L1 * SC1P;
    int ac4 = tid & 15;
    for (int kb = 0; kb < 32; kb++) {
        int kk = kb >> 3;
        int cb = (kb & 7) << 6;
        // A tile: 256 rows x 64 ch -> As[c][m]
#pragma unroll
        for (int q = 0; q < 16; q++) {
            int idx = tid + q * 256;
            int m = idx >> 4;
            int row = t0 + kk + m;
            float4 v = make_float4(0.f, 0.f, 0.f, 0.f);
            if (row < L1)
                v = *(const float4*)&pAbase[(size_t)row * SC1P + cb + ac4 * 4];
            As[(ac4*4+0)*SAS + m] = v.x;
            As[(ac4*4+1)*SAS + m] = v.y;
            As[(ac4*4+2)*SAS + m] = v.z;
            As[(ac4*4+3)*SAS + m] = v.w;
        }
        const float4* pB = (const float4*)(g_wpad + (kk * SC1P + cb) * 64);
#pragma unroll
        for (int q = 0; q < 4; q++)
            ((float4*)Bs)[tid + q * 256] = pB[tid + q * 256];
        __syncthreads();
#pragma unroll
        for (int k = 0; k < 64; k++) {
            float4 wv = *(const float4*)&Bs[k * 64 + n0];
            unsigned long long wp0 = pack2(wv.x), wp1 = pack2(wv.y);
            unsigned long long wp2 = pack2(wv.z), wp3 = pack2(wv.w);
            const unsigned long long* pa = (const unsigned long long*)&As[k * SAS + m0];
#pragma unroll
            for (int p = 0; p < 8; p++) {
                unsigned long long av = pa[p];
                acc2[p][0] = ffma2(av, wp0, acc2[p][0]);
                acc2[p][1] = ffma2(av, wp1, acc2[p][1]);
                acc2[p][2] = ffma2(av, wp2, acc2[p][2]);
                acc2[p][3] = ffma2(av, wp3, acc2[p][3]);
            }
        }
        __syncthreads();
    }

    // ---- epilogue: Z = relu(y0 + b0) ----
#pragma unroll
    for (int p = 0; p < 8; p++)
#pragma unroll
        for (int j = 0; j < 4; j++) {
            float lo, hi;
            unpack2(acc2[p][j], lo, hi);
            Z[(m0 + 2*p    ) * SZ + n0 + j] = fmaxf(lo + b0s[n0 + j], 0.f);
            Z[(m0 + 2*p + 1) * SZ + n0 + j] = fmaxf(hi + b0s[n0 + j], 0.f);
        }
#pragma unroll
    for (int q = 0; q < 16; q++) {
        int idx = tid + q * 256;
        Wm[(idx & 63) * SW + (idx >> 6)] = w1[idx];
    }
    __syncthreads();

    float a2[16][4];
#pragma unroll
    for (int i = 0; i < 16; i++)
#pragma unroll
        for (int j = 0; j < 4; j++) a2[i][j] = b1s[n0 + j];
#pragma unroll 2
    for (int c = 0; c < 64; c++) {
        float4 wv = *(const float4*)&Wm[c * SW + n0];
#pragma unroll
        for (int i = 0; i < 16; i++) {
            float zi = Z[(m0 + i) * SZ + c];
            a2[i][0] += zi * wv.x; a2[i][1] += zi * wv.y;
            a2[i][2] += zi * wv.z; a2[i][3] += zi * wv.w;
        }
    }
    __syncthreads();
#pragma unroll
    for (int i = 0; i < 16; i++)
#pragma unroll
        for (int j = 0; j < 4; j++)
            Z[(m0 + i) * SZ + n0 + j] = fmaxf(a2[i][j], 0.f);
#pragma unroll
    for (int q = 0; q < 4; q++) {
        int idx = tid + q * 256;
        Wm[(idx >> 6) * SW + (idx & 63)] = w2[idx];
    }
    __syncthreads();
    int o3 = tid & 15;
    int mb = tid >> 4;
#pragma unroll
    for (int g2 = 0; g2 < 16; g2++) {
        int m = mb + g2 * 16;
        float s = b2s[o3];
#pragma unroll 16
        for (int c = 0; c < 64; c++) s += Wm[o3 * SW + c] * Z[m * SZ + c];
        int t = t0 + m;
        if (t < L2) g_h2[(size_t)(b * L2 + t) * H2 + o3] = s;
    }
}

// ============================================================
// become_constant + sig2 + linear
// ============================================================
__global__ __launch_bounds__(256) void k_sig2(
    const int* __restrict__ lengths,
    const float* __restrict__ lw, const float* __restrict__ lb,
    float* __restrict__ out)
{
    __shared__ float hs[129][16];
    __shared__ float s2s[SIGC2];
    int b = blockIdx.x, tid = threadIdx.x;
    int adj = lengths[b] - 2 * KS + 2;
    if (adj < 1) adj = 1;
    if (adj > L2) adj = L2;
    int i = tid >> 4, j = tid & 15;
    float acc = 0.f;
    for (int c0 = 0; c0 < adj; c0 += 128) {
        for (int idx = tid; idx < 129 * 16; idx += 256) {
            int r = idx >> 4, c = idx & 15;
            int row = c0 - 1 + r;
            hs[r][c] = (row >= 0 && row < L2) ? g_h2[(size_t)(b * L2 + row) * H2 + c] : 0.f;
        }
        __syncthreads();
        int tend = min(c0 + 128, adj);
        for (int t = c0; t < tend; t++) {
            int r = t - c0 + 1;
            float hpi = hs[r-1][i], hpj = hs[r-1][j];
            float dxi = hs[r][i] - hpi, dxj = hs[r][j] - hpj;
            acc += hpi * dxj + 0.5f * dxi * dxj;
        }
        __syncthreads();
    }
    s2s[16 + tid] = acc;
    if (tid < 16) s2s[tid] = g_h2[(size_t)(b * L2 + adj - 1) * H2 + tid];
    __syncthreads();
    if (tid < OUTC) {
        float v = lb[tid];
        for (int c = 0; c < SIGC2; c++) v += lw[tid * SIGC2 + c] * s2s[c];
        out[b * OUTC + tid] = v;
    }
}

// ============================================================
extern "C" void kernel_launch(void* const* d_in, const int* in_sizes, int n_in,
                              void* d_out, int out_size) {
    const float* x      = (const float*)d_in[0];
    const int*   lens   = (const int*)  d_in[1];
    const float* a1_w0  = (const float*)d_in[2];
    const float* a1_b0  = (const float*)d_in[3];
    const float* a1_w1  = (const float*)d_in[4];
    const float* a1_b1  = (const float*)d_in[5];
    const float* a1_w2  = (const float*)d_in[6];
    const float* a1_b2  = (const float*)d_in[7];
    const float* a2_w0  = (const float*)d_in[8];
    const float* a2_b0  = (const float*)d_in[9];
    const float* a2_w1  = (const float*)d_in[10];
    const float* a2_b1  = (const float*)d_in[11];
    const float* a2_w2  = (const float*)d_in[12];
    const float* a2_b2  = (const float*)d_in[13];
    const float* lin_w  = (const float*)d_in[14];
    const float* lin_b  = (const float*)d_in[15];
    float* out = (float*)d_out;

    static bool attr_set = false;
    if (!attr_set) {
        cudaFuncSetAttribute(k_conv2, cudaFuncAttributeMaxDynamicSharedMemorySize, DSMB);
        attr_set = true;
    }

    k_repack<<<512, 256>>>(a2_w0);
    k_aug1<<<dim3(8, B_), 128>>>(x, a1_w0, a1_b0, a1_w1, a1_b1, a1_w2, a1_b2);
    k_sig1_sum<<<dim3(NC1, B_), 512>>>();
    k_sig1_prefix<<<B_, 512>>>();
    k_sig1_write<<<dim3(NC1, B_), 512>>>();
    k_conv2<<<dim3(4, B_), 256, DSMB>>>(a2_b0, a2_w1, a2_b1, a2_w2, a2_b2);
    k_sig2<<<B_, 256>>>(lens, lin_w, lin_b, out);
}

// round 9
// speedup vs baseline: 2.4089x; 1.4178x over previous
#include <cuda_runtime.h>
#include <cuda_bf16.h>
#include <cstdint>

#define B_    64
#define S_    1024
#define CIN   5
#define KS    4
#define H1    64
#define H2    16
#define OUTC  32
#define L1    1021
#define C1    22
#define SIGC1 506
#define SC1P  512
#define L2    1018
#define SIGC2 272
#define NC1   16
#define CH1   64

// ---- conv2 HMMA geometry: tile M=128 rows x N=64, K-chunks 64ch x (4 taps x 8) ----
// smem (bytes): Ah[128][72h]=18432, Al same, Bh[64][72h]=9216, Bl same
#define OFF_AH  0u
#define OFF_AL  18432u
#define OFF_BH  36864u
#define OFF_BL  46080u
// epilogue overlay
#define OFF_Z   0u           // f32 [128][68] = 34816
#define OFF_W1  36864u       // f32 [64][64] transposed = 16384
#define OFF_W2  53248u       // f32 [16][64] = 4096
#define OFF_BS  57344u       // f32 b0[64] b1[64] b2[16]
#define DSMB    57920u

// ---- scratch ----
__device__ float g_h[B_ * L1 * C1];
__device__ __nv_bfloat16 g_s1h[(size_t)B_ * L1 * SC1P];
__device__ __nv_bfloat16 g_s1l[(size_t)B_ * L1 * SC1P];
__device__ __nv_bfloat16 g_wbh[KS * 64 * SC1P];    // [kk][o][c]
__device__ __nv_bfloat16 g_wbl[KS * 64 * SC1P];
__device__ float g_csum[B_ * NC1 * SC1P];
__device__ float g_h2[B_ * L2 * H2];

__device__ __forceinline__ void mma_bf16(
    float& c0, float& c1, float& c2, float& c3,
    uint32_t a0, uint32_t a1, uint32_t a2, uint32_t a3,
    uint32_t b0, uint32_t b1) {
    asm volatile(
        "mma.sync.aligned.m16n8k16.row.col.f32.bf16.bf16.f32 "
        "{%0,%1,%2,%3}, {%4,%5,%6,%7}, {%8,%9}, {%0,%1,%2,%3};"
        : "+f"(c0), "+f"(c1), "+f"(c2), "+f"(c3)
        : "r"(a0), "r"(a1), "r"(a2), "r"(a3), "r"(b0), "r"(b1));
}

// ============================================================
// Repack a2_w0 (O,C,K) -> bf16 hi/lo [kk][o][512c]
// ============================================================
__global__ void k_repack(const float* __restrict__ w0) {
    int idx = blockIdx.x * blockDim.x + threadIdx.x;   // 0..131071
    int c  = idx & 511;
    int o  = (idx >> 9) & 63;
    int kk = idx >> 15;
    float v = (c < SIGC1) ? w0[(o * SIGC1 + c) * KS + kk] : 0.f;
    __nv_bfloat16 hi = __float2bfloat16(v);
    __nv_bfloat16 lo = __float2bfloat16(v - __bfloat162float(hi));
    g_wbh[idx] = hi;
    g_wbl[idx] = lo;
}

// ============================================================
// Augment 1
// ============================================================
__global__ __launch_bounds__(128) void k_aug1(
    const float* __restrict__ x,
    const float* __restrict__ w0, const float* __restrict__ b0,
    const float* __restrict__ w1, const float* __restrict__ b1,
    const float* __restrict__ w2, const float* __restrict__ b2)
{
    __shared__ float w0s[H1*CIN*KS], w1s[H1*H1], w2s[H2*H1];
    __shared__ float b0s[H1], b1s[H1], b2s[H2];
    int tid = threadIdx.x;
    for (int i = tid; i < H1*CIN*KS; i += 128) w0s[i] = w0[i];
    for (int i = tid; i < H1*H1;     i += 128) w1s[i] = w1[i];
    for (int i = tid; i < H2*H1;     i += 128) w2s[i] = w2[i];
    if (tid < H1) { b0s[tid] = b0[tid]; b1s[tid] = b1[tid]; }
    if (tid < H2) b2s[tid] = b2[tid];
    __syncthreads();

    int b = blockIdx.y;
    int t = blockIdx.x * 128 + tid;
    if (t >= L1) return;

    float xr[KS][CIN];
#pragma unroll
    for (int k = 0; k < KS; k++)
#pragma unroll
        for (int c = 0; c < CIN; c++)
            xr[k][c] = x[((size_t)(b * S_) + t + k) * CIN + c];

    float z1[H1];
#pragma unroll
    for (int o = 0; o < H1; o++) {
        float s = b0s[o];
#pragma unroll
        for (int c = 0; c < CIN; c++)
#pragma unroll
            for (int k = 0; k < KS; k++)
                s += w0s[(o*CIN + c)*KS + k] * xr[k][c];
        z1[o] = fmaxf(s, 0.f);
    }
    float z3[H2];
#pragma unroll
    for (int o = 0; o < H2; o++) z3[o] = b2s[o];
    for (int o2 = 0; o2 < H1; o2++) {
        float s = b1s[o2];
#pragma unroll
        for (int c = 0; c < H1; c++) s += w1s[o2*H1 + c] * z1[c];
        s = fmaxf(s, 0.f);
#pragma unroll
        for (int o = 0; o < H2; o++) z3[o] += w2s[o*H1 + o2] * s;
    }
    float* hrow = &g_h[(size_t)(b * L1 + t) * C1];
#pragma unroll
    for (int c = 0; c < CIN; c++) hrow[c] = xr[KS-1][c];
    hrow[CIN] = (float)t * (1.0f / (float)(L1 - 1));
#pragma unroll
    for (int o = 0; o < H2; o++) hrow[CIN + 1 + o] = z3[o];
}

// ============================================================
// Sig1 passes
// ============================================================
__global__ __launch_bounds__(512) void k_sig1_sum() {
    __shared__ float hs[CH1 + 1][C1];
    int b = blockIdx.y, nc = blockIdx.x, tid = threadIdx.x;
    int c0 = nc * CH1;
    for (int idx = tid; idx < (CH1 + 1) * C1; idx += 512) {
        int r = idx / C1, c = idx - r * C1;
        int row = c0 - 1 + r;
        hs[r][c] = (row >= 0 && row < L1) ? g_h[(size_t)(b * L1 + row) * C1 + c] : 0.f;
    }
    __syncthreads();
    if (tid >= C1 * C1) return;
    int i = tid / C1, j = tid - i * C1;
    float acc = 0.f;
    int tend = min(c0 + CH1, L1);
    for (int t = c0; t < tend; t++) {
        int r = t - c0 + 1;
        float hpi = hs[r-1][i], hpj = hs[r-1][j];
        float dxi = hs[r][i] - hpi, dxj = hs[r][j] - hpj;
        acc += hpi * dxj + 0.5f * dxi * dxj;
    }
    g_csum[(b * NC1 + nc) * SC1P + tid] = acc;
}

__global__ void k_sig1_prefix() {
    int b = blockIdx.x, tid = threadIdx.x;
    if (tid >= C1 * C1) return;
    float run = 0.f;
    for (int nc = 0; nc < NC1; nc++) {
        int idx = (b * NC1 + nc) * SC1P + tid;
        float v = g_csum[idx];
        g_csum[idx] = run;
        run += v;
    }
}

__device__ __forceinline__ void store_hl(size_t base, int ch, float v) {
    __nv_bfloat16 hi = __float2bfloat16(v);
    __nv_bfloat16 lo = __float2bfloat16(v - __bfloat162float(hi));
    g_s1h[base + ch] = hi;
    g_s1l[base + ch] = lo;
}

__global__ __launch_bounds__(512) void k_sig1_write() {
    __shared__ float hs[CH1 + 1][C1];
    int b = blockIdx.y, nc = blockIdx.x, tid = threadIdx.x;
    int c0 = nc * CH1;
    for (int idx = tid; idx < (CH1 + 1) * C1; idx += 512) {
        int r = idx / C1, c = idx - r * C1;
        int row = c0 - 1 + r;
        hs[r][c] = (row >= 0 && row < L1) ? g_h[(size_t)(b * L1 + row) * C1 + c] : 0.f;
    }
    __syncthreads();
    int tend = min(c0 + CH1, L1);
    if (tid < C1 * C1) {
        int i = tid / C1, j = tid - i * C1;
        float acc = g_csum[(b * NC1 + nc) * SC1P + tid];
        for (int t = c0; t < tend; t++) {
            int r = t - c0 + 1;
            float hpi = hs[r-1][i], hpj = hs[r-1][j];
            float dxi = hs[r][i] - hpi, dxj = hs[r][j] - hpj;
            acc += hpi * dxj + 0.5f * dxi * dxj;
            store_hl((size_t)(b * L1 + t) * SC1P, C1 + tid, acc);
        }
    } else {
        int c = tid - C1 * C1;
        int ch = (c < C1) ? c : (C1 * C1 + c);
        for (int t = c0; t < tend; t++) {
            int r = t - c0 + 1;
            float v = (c < C1) ? hs[r][c] : 0.f;
            store_hl((size_t)(b * L1 + t) * SC1P, ch, v);
        }
    }
}

// ============================================================
// Conv stack 2: split-bf16 HMMA (mma.sync m16n8k16) + fused epilogue
// 256 thr = 8 warps: warp_m = wid&3 (32 rows), warp_n = wid>>2 (32 cols)
// ============================================================
__global__ __launch_bounds__(256, 2) void k_conv2_mma(
    const float* __restrict__ b0,
    const float* __restrict__ w1, const float* __restrict__ b1,
    const float* __restrict__ w2, const float* __restrict__ b2)
{
    extern __shared__ __align__(16) char dsm[];
    int tid = threadIdx.x;
    int lane = tid & 31, wid = tid >> 5;
    int warp_m = wid & 3, warp_n = wid >> 2;
    int b = blockIdx.y, t0 = blockIdx.x * 128;
    int g = lane >> 2, t4 = lane & 3;

    float C[2][4][4];
#pragma unroll
    for (int mt = 0; mt < 2; mt++)
#pragma unroll
        for (int nt = 0; nt < 4; nt++)
#pragma unroll
            for (int q = 0; q < 4; q++) C[mt][nt][q] = 0.f;

    const __nv_bfloat16* gAh = g_s1h + (size_t)b * L1 * SC1P;
    const __nv_bfloat16* gAl = g_s1l + (size_t)b * L1 * SC1P;

    for (int ch = 0; ch < 32; ch++) {
        int kk = ch >> 3, cb = (ch & 7) << 6;
        // ---- A fill: 128 rows x 64 ch, hi+lo; row stride 144 B ----
#pragma unroll
        for (int it = 0; it < 4; it++) {
            int idx = tid + it * 256;         // 0..1023
            int m = idx >> 3, g8 = idx & 7;
            int t = t0 + kk + m;
            bool ok = (t < L1);
            uint4 vh = make_uint4(0,0,0,0), vl = make_uint4(0,0,0,0);
            if (ok) {
                vh = *(const uint4*)(gAh + (size_t)t * SC1P + cb + g8 * 8);
                vl = *(const uint4*)(gAl + (size_t)t * SC1P + cb + g8 * 8);
            }
            *(uint4*)(dsm + OFF_AH + m * 144 + g8 * 16) = vh;
            *(uint4*)(dsm + OFF_AL + m * 144 + g8 * 16) = vl;
        }
        // ---- B fill: 64 rows(o) x 64 ch ----
#pragma unroll
        for (int it = 0; it < 2; it++) {
            int idx = tid + it * 256;         // 0..511
            int o = idx >> 3, g8 = idx & 7;
            const __nv_bfloat16* src = g_wbh + (size_t)(kk * 64 + o) * SC1P + cb + g8 * 8;
            const __nv_bfloat16* srl = g_wbl + (size_t)(kk * 64 + o) * SC1P + cb + g8 * 8;
            *(uint4*)(dsm + OFF_BH + o * 144 + g8 * 16) = *(const uint4*)src;
            *(uint4*)(dsm + OFF_BL + o * 144 + g8 * 16) = *(const uint4*)srl;
        }
        __syncthreads();

#pragma unroll
        for (int ks = 0; ks < 4; ks++) {
            int kc = ks * 16;
            int koff = (kc + 2 * t4) * 2;     // byte offset within row
            uint32_t ah[2][4], al[2][4];
#pragma unroll
            for (int mt = 0; mt < 2; mt++) {
                int rbase = (warp_m * 32 + mt * 16 + g) * 144;
                ah[mt][0] = *(const uint32_t*)(dsm + OFF_AH + rbase + koff);
                ah[mt][1] = *(const uint32_t*)(dsm + OFF_AH + rbase + 1152 + koff);
                ah[mt][2] = *(const uint32_t*)(dsm + OFF_AH + rbase + koff + 16);
                ah[mt][3] = *(const uint32_t*)(dsm + OFF_AH + rbase + 1152 + koff + 16);
                al[mt][0] = *(const uint32_t*)(dsm + OFF_AL + rbase + koff);
                al[mt][1] = *(const uint32_t*)(dsm + OFF_AL + rbase + 1152 + koff);
                al[mt][2] = *(const uint32_t*)(dsm + OFF_AL + rbase + koff + 16);
                al[mt][3] = *(const uint32_t*)(dsm + OFF_AL + rbase + 1152 + koff + 16);
            }
            uint32_t bh[4][2], bl[4][2];
#pragma unroll
            for (int nt = 0; nt < 4; nt++) {
                int nbase = (warp_n * 32 + nt * 8 + g) * 144;
                bh[nt][0] = *(const uint32_t*)(dsm + OFF_BH + nbase + koff);
                bh[nt][1] = *(const uint32_t*)(dsm + OFF_BH + nbase + koff + 16);
                bl[nt][0] = *(const uint32_t*)(dsm + OFF_BL + nbase + koff);
                bl[nt][1] = *(const uint32_t*)(dsm + OFF_BL + nbase + koff + 16);
            }
#pragma unroll
            for (int mt = 0; mt < 2; mt++)
#pragma unroll
                for (int nt = 0; nt < 4; nt++) {
                    float* c = C[mt][nt];
                    mma_bf16(c[0], c[1], c[2], c[3],
                             ah[mt][0], ah[mt][1], ah[mt][2], ah[mt][3],
                             bh[nt][0], bh[nt][1]);
                    mma_bf16(c[0], c[1], c[2], c[3],
                             ah[mt][0], ah[mt][1], ah[mt][2], ah[mt][3],
                             bl[nt][0], bl[nt][1]);
                    mma_bf16(c[0], c[1], c[2], c[3],
                             al[mt][0], al[mt][1], al[mt][2], al[mt][3],
                             bh[nt][0], bh[nt][1]);
                }
        }
        __syncthreads();
    }

    // ---- epilogue: C -> Z[128][68] f32; W1 (transposed), W2, biases into smem ----
#pragma unroll
    for (int mt = 0; mt < 2; mt++)
#pragma unroll
        for (int nt = 0; nt < 4; nt++) {
            int row = warp_m * 32 + mt * 16 + g;
            int col = warp_n * 32 + nt * 8 + 2 * t4;
            *(float2*)(dsm + OFF_Z + row * 272 + col * 4) =
                make_float2(C[mt][nt][0], C[mt][nt][1]);
            *(float2*)(dsm + OFF_Z + (row + 8) * 272 + col * 4) =
                make_float2(C[mt][nt][2], C[mt][nt][3]);
        }
    float* W1t = (float*)(dsm + OFF_W1);   // [c][o]
    float* W2s = (float*)(dsm + OFF_W2);   // [o3][o2]
    float* bss = (float*)(dsm + OFF_BS);
#pragma unroll
    for (int q = 0; q < 16; q++) {
        int idx = tid + q * 256;           // o*64+c
        W1t[(idx & 63) * 64 + (idx >> 6)] = w1[idx];
    }
#pragma unroll
    for (int q = 0; q < 4; q++) {
        int idx = tid + q * 256;
        W2s[idx] = w2[idx];
    }
    if (tid < 64) { bss[tid] = b0[tid]; bss[64 + tid] = b1[tid]; }
    if (tid < 16) bss[128 + tid] = b2[tid];
    __syncthreads();

    int row = tid >> 1, half = tid & 1;
    int o2b = half * 32;
    float z2[32];
#pragma unroll
    for (int o = 0; o < 32; o++) z2[o] = bss[64 + o2b + o];
#pragma unroll 4
    for (int c = 0; c < 64; c++) {
        float zc = fmaxf(*(const float*)(dsm + OFF_Z + row * 272 + c * 4) + bss[c], 0.f);
        const float4* wv = (const float4*)&W1t[c * 64 + o2b];
#pragma unroll
        for (int q8 = 0; q8 < 8; q8++) {
            float4 w4 = wv[q8];
            z2[q8*4+0] += zc * w4.x; z2[q8*4+1] += zc * w4.y;
            z2[q8*4+2] += zc * w4.z; z2[q8*4+3] += zc * w4.w;
        }
    }
#pragma unroll
    for (int o = 0; o < 32; o++) z2[o] = fmaxf(z2[o], 0.f);

    float p[16];
#pragma unroll
    for (int o3 = 0; o3 < 16; o3++) {
        float s = 0.f;
        const float4* wv = (const float4*)&W2s[o3 * 64 + o2b];
#pragma unroll
        for (int q8 = 0; q8 < 8; q8++) {
            float4 w4 = wv[q8];
            s += w4.x * z2[q8*4+0] + w4.y * z2[q8*4+1]
               + w4.z * z2[q8*4+2] + w4.w * z2[q8*4+3];
        }
        p[o3] = s;
    }
#pragma unroll
    for (int o3 = 0; o3 < 16; o3++)
        p[o3] += __shfl_xor_sync(0xffffffffu, p[o3], 1);

    int t = t0 + row;
    if (t < L2) {
        float4 v0, v1;
        int ob = half * 8;
        v0 = make_float4(p[ob+0] + bss[128+ob+0], p[ob+1] + bss[128+ob+1],
                         p[ob+2] + bss[128+ob+2], p[ob+3] + bss[128+ob+3]);
        v1 = make_float4(p[ob+4] + bss[128+ob+4], p[ob+5] + bss[128+ob+5],
                         p[ob+6] + bss[128+ob+6], p[ob+7] + bss[128+ob+7]);
        float* dst = &g_h2[(size_t)(b * L2 + t) * H2 + ob];
        *(float4*)dst = v0;
        *(float4*)(dst + 4) = v1;
    }
}

// ============================================================
// become_constant + sig2 + linear
// ============================================================
__global__ __launch_bounds__(256) void k_sig2(
    const int* __restrict__ lengths,
    const float* __restrict__ lw, const float* __restrict__ lb,
    float* __restrict__ out)
{
    __shared__ float hs[129][16];
    __shared__ float s2s[SIGC2];
    int b = blockIdx.x, tid = threadIdx.x;
    int adj = lengths[b] - 2 * KS + 2;
    if (adj < 1) adj = 1;
    if (adj > L2) adj = L2;
    int i = tid >> 4, j = tid & 15;
    float acc = 0.f;
    for (int c0 = 0; c0 < adj; c0 += 128) {
        for (int idx = tid; idx < 129 * 16; idx += 256) {
            int r = idx >> 4, c = idx & 15;
            int row = c0 - 1 + r;
            hs[r][c] = (row >= 0 && row < L2) ? g_h2[(size_t)(b * L2 + row) * H2 + c] : 0.f;
        }
        __syncthreads();
        int tend = min(c0 + 128, adj);
        for (int t = c0; t < tend; t++) {
            int r = t - c0 + 1;
            float hpi = hs[r-1][i], hpj = hs[r-1][j];
            float dxi = hs[r][i] - hpi, dxj = hs[r][j] - hpj;
            acc += hpi * dxj + 0.5f * dxi * dxj;
        }
        __syncthreads();
    }
    s2s[16 + tid] = acc;
    if (tid < 16) s2s[tid] = g_h2[(size_t)(b * L2 + adj - 1) * H2 + tid];
    __syncthreads();
    if (tid < OUTC) {
        float v = lb[tid];
        for (int c = 0; c < SIGC2; c++) v += lw[tid * SIGC2 + c] * s2s[c];
        out[b * OUTC + tid] = v;
    }
}

// ============================================================
extern "C" void kernel_launch(void* const* d_in, const int* in_sizes, int n_in,
                              void* d_out, int out_size) {
    const float* x      = (const float*)d_in[0];
    const int*   lens   = (const int*)  d_in[1];
    const float* a1_w0  = (const float*)d_in[2];
    const float* a1_b0  = (const float*)d_in[3];
    const float* a1_w1  = (const float*)d_in[4];
    const float* a1_b1  = (const float*)d_in[5];
    const float* a1_w2  = (const float*)d_in[6];
    const float* a1_b2  = (const float*)d_in[7];
    const float* a2_w0  = (const float*)d_in[8];
    const float* a2_b0  = (const float*)d_in[9];
    const float* a2_w1  = (const float*)d_in[10];
    const float* a2_b1  = (const float*)d_in[11];
    const float* a2_w2  = (const float*)d_in[12];
    const float* a2_b2  = (const float*)d_in[13];
    const float* lin_w  = (const float*)d_in[14];
    const float* lin_b  = (const float*)d_in[15];
    float* out = (float*)d_out;

    static bool attr_set = false;
    if (!attr_set) {
        cudaFuncSetAttribute(k_conv2_mma, cudaFuncAttributeMaxDynamicSharedMemorySize, DSMB);
        attr_set = true;
    }

    k_repack<<<512, 256>>>(a2_w0);
    k_aug1<<<dim3(8, B_), 128>>>(x, a1_w0, a1_b0, a1_w1, a1_b1, a1_w2, a1_b2);
    k_sig1_sum<<<dim3(NC1, B_), 512>>>();
    k_sig1_prefix<<<B_, 512>>>();
    k_sig1_write<<<dim3(NC1, B_), 512>>>();
    k_conv2_mma<<<dim3(8, B_), 256, DSMB>>>(a2_b0, a2_w1, a2_b1, a2_w2, a2_b2);
    k_sig2<<<B_, 256>>>(lens, lin_w, lin_b, out);
}

// round 10
// speedup vs baseline: 2.6135x; 1.0849x over previous
#include <cuda_runtime.h>
#include <cuda_bf16.h>
#include <cstdint>

#define B_    64
#define S_    1024
#define CIN   5
#define KS    4
#define H1    64
#define H2    16
#define OUTC  32
#define L1    1021
#define C1    22
#define SIGC1 506
#define SC1P  512
#define L2    1018
#define SIGC2 272
#define NC1   16
#define CH1   64

// ---- conv2 HMMA geometry ----
// A halo: 131 rows x 64ch hi/lo, row stride 144 B
#define OFF_AH  0u
#define OFF_AL  18864u
#define OFF_B   37728u             // 2 bufs x (Bh 9216 + Bl 9216)
#define BBUF(i) (OFF_B + (uint32_t)(i) * 18432u)
// epilogue overlay
#define OFF_Z   0u                 // f32 [128][68] = 34816
#define OFF_W1  36864u             // f32 [64][64] transposed
#define OFF_W2  53248u             // f32 [16][64]
#define OFF_BS  57344u
#define DSMB    74592u

// ---- scratch ----
__device__ float g_h[B_ * L1 * C1];
__device__ __nv_bfloat16 g_s1h[(size_t)B_ * L1 * SC1P];
__device__ __nv_bfloat16 g_s1l[(size_t)B_ * L1 * SC1P];
__device__ __nv_bfloat16 g_wbh[KS * 64 * SC1P];    // [kk][o][c]
__device__ __nv_bfloat16 g_wbl[KS * 64 * SC1P];
__device__ float g_csum[B_ * NC1 * SC1P];
__device__ float g_h2[B_ * L2 * H2];

__device__ __forceinline__ void mma_bf16(
    float& c0, float& c1, float& c2, float& c3,
    uint32_t a0, uint32_t a1, uint32_t a2, uint32_t a3,
    uint32_t b0, uint32_t b1) {
    asm volatile(
        "mma.sync.aligned.m16n8k16.row.col.f32.bf16.bf16.f32 "
        "{%0,%1,%2,%3}, {%4,%5,%6,%7}, {%8,%9}, {%0,%1,%2,%3};"
        : "+f"(c0), "+f"(c1), "+f"(c2), "+f"(c3)
        : "r"(a0), "r"(a1), "r"(a2), "r"(a3), "r"(b0), "r"(b1));
}

// ============================================================
// Repack a2_w0 (O,C,K) -> bf16 hi/lo [kk][o][512c]
// ============================================================
__global__ void k_repack(const float* __restrict__ w0) {
    int idx = blockIdx.x * blockDim.x + threadIdx.x;   // 0..131071
    int c  = idx & 511;
    int o  = (idx >> 9) & 63;
    int kk = idx >> 15;
    float v = (c < SIGC1) ? w0[(o * SIGC1 + c) * KS + kk] : 0.f;
    __nv_bfloat16 hi = __float2bfloat16(v);
    __nv_bfloat16 lo = __float2bfloat16(v - __bfloat162float(hi));
    g_wbh[idx] = hi;
    g_wbl[idx] = lo;
}

// ============================================================
// Augment 1
// ============================================================
__global__ __launch_bounds__(128) void k_aug1(
    const float* __restrict__ x,
    const float* __restrict__ w0, const float* __restrict__ b0,
    const float* __restrict__ w1, const float* __restrict__ b1,
    const float* __restrict__ w2, const float* __restrict__ b2)
{
    __shared__ float w0s[H1*CIN*KS], w1s[H1*H1], w2s[H2*H1];
    __shared__ float b0s[H1], b1s[H1], b2s[H2];
    int tid = threadIdx.x;
    for (int i = tid; i < H1*CIN*KS; i += 128) w0s[i] = w0[i];
    for (int i = tid; i < H1*H1;     i += 128) w1s[i] = w1[i];
    for (int i = tid; i < H2*H1;     i += 128) w2s[i] = w2[i];
    if (tid < H1) { b0s[tid] = b0[tid]; b1s[tid] = b1[tid]; }
    if (tid < H2) b2s[tid] = b2[tid];
    __syncthreads();

    int b = blockIdx.y;
    int t = blockIdx.x * 128 + tid;
    if (t >= L1) return;

    float xr[KS][CIN];
#pragma unroll
    for (int k = 0; k < KS; k++)
#pragma unroll
        for (int c = 0; c < CIN; c++)
            xr[k][c] = x[((size_t)(b * S_) + t + k) * CIN + c];

    float z1[H1];
#pragma unroll
    for (int o = 0; o < H1; o++) {
        float s = b0s[o];
#pragma unroll
        for (int c = 0; c < CIN; c++)
#pragma unroll
            for (int k = 0; k < KS; k++)
                s += w0s[(o*CIN + c)*KS + k] * xr[k][c];
        z1[o] = fmaxf(s, 0.f);
    }
    float z3[H2];
#pragma unroll
    for (int o = 0; o < H2; o++) z3[o] = b2s[o];
    for (int o2 = 0; o2 < H1; o2++) {
        float s = b1s[o2];
#pragma unroll
        for (int c = 0; c < H1; c++) s += w1s[o2*H1 + c] * z1[c];
        s = fmaxf(s, 0.f);
#pragma unroll
        for (int o = 0; o < H2; o++) z3[o] += w2s[o*H1 + o2] * s;
    }
    float* hrow = &g_h[(size_t)(b * L1 + t) * C1];
#pragma unroll
    for (int c = 0; c < CIN; c++) hrow[c] = xr[KS-1][c];
    hrow[CIN] = (float)t * (1.0f / (float)(L1 - 1));
#pragma unroll
    for (int o = 0; o < H2; o++) hrow[CIN + 1 + o] = z3[o];
}

// ============================================================
// Sig1 passes
// ============================================================
__global__ __launch_bounds__(512) void k_sig1_sum() {
    __shared__ float hs[CH1 + 1][C1];
    int b = blockIdx.y, nc = blockIdx.x, tid = threadIdx.x;
    int c0 = nc * CH1;
    for (int idx = tid; idx < (CH1 + 1) * C1; idx += 512) {
        int r = idx / C1, c = idx - r * C1;
        int row = c0 - 1 + r;
        hs[r][c] = (row >= 0 && row < L1) ? g_h[(size_t)(b * L1 + row) * C1 + c] : 0.f;
    }
    __syncthreads();
    if (tid >= C1 * C1) return;
    int i = tid / C1, j = tid - i * C1;
    float acc = 0.f;
    int tend = min(c0 + CH1, L1);
    for (int t = c0; t < tend; t++) {
        int r = t - c0 + 1;
        float hpi = hs[r-1][i], hpj = hs[r-1][j];
        float dxi = hs[r][i] - hpi, dxj = hs[r][j] - hpj;
        acc += hpi * dxj + 0.5f * dxi * dxj;
    }
    g_csum[(b * NC1 + nc) * SC1P + tid] = acc;
}

__global__ void k_sig1_prefix() {
    int b = blockIdx.x, tid = threadIdx.x;
    if (tid >= C1 * C1) return;
    float run = 0.f;
    for (int nc = 0; nc < NC1; nc++) {
        int idx = (b * NC1 + nc) * SC1P + tid;
        float v = g_csum[idx];
        g_csum[idx] = run;
        run += v;
    }
}

__device__ __forceinline__ void store_hl(size_t base, int ch, float v) {
    __nv_bfloat16 hi = __float2bfloat16(v);
    __nv_bfloat16 lo = __float2bfloat16(v - __bfloat162float(hi));
    g_s1h[base + ch] = hi;
    g_s1l[base + ch] = lo;
}

__global__ __launch_bounds__(512) void k_sig1_write() {
    __shared__ float hs[CH1 + 1][C1];
    int b = blockIdx.y, nc = blockIdx.x, tid = threadIdx.x;
    int c0 = nc * CH1;
    for (int idx = tid; idx < (CH1 + 1) * C1; idx += 512) {
        int r = idx / C1, c = idx - r * C1;
        int row = c0 - 1 + r;
        hs[r][c] = (row >= 0 && row < L1) ? g_h[(size_t)(b * L1 + row) * C1 + c] : 0.f;
    }
    __syncthreads();
    int tend = min(c0 + CH1, L1);
    if (tid < C1 * C1) {
        int i = tid / C1, j = tid - i * C1;
        float acc = g_csum[(b * NC1 + nc) * SC1P + tid];
        for (int t = c0; t < tend; t++) {
            int r = t - c0 + 1;
            float hpi = hs[r-1][i], hpj = hs[r-1][j];
            float dxi = hs[r][i] - hpi, dxj = hs[r][j] - hpj;
            acc += hpi * dxj + 0.5f * dxi * dxj;
            store_hl((size_t)(b * L1 + t) * SC1P, C1 + tid, acc);
        }
    } else {
        int c = tid - C1 * C1;
        int ch = (c < C1) ? c : (C1 * C1 + c);
        for (int t = c0; t < tend; t++) {
            int r = t - c0 + 1;
            float v = (c < C1) ? hs[r][c] : 0.f;
            store_hl((size_t)(b * L1 + t) * SC1P, ch, v);
        }
    }
}

// ============================================================
// Conv stack 2: split-bf16 HMMA, A-halo reuse across taps,
// B double-buffered, fused epilogue
// ============================================================
__global__ __launch_bounds__(256, 2) void k_conv2_mma(
    const float* __restrict__ b0,
    const float* __restrict__ w1, const float* __restrict__ b1,
    const float* __restrict__ w2, const float* __restrict__ b2)
{
    extern __shared__ __align__(16) char dsm[];
    int tid = threadIdx.x;
    int lane = tid & 31, wid = tid >> 5;
    int warp_m = wid & 3, warp_n = wid >> 2;
    int b = blockIdx.y, t0 = blockIdx.x * 128;
    int g = lane >> 2, t4 = lane & 3;

    float C[2][4][4];
#pragma unroll
    for (int mt = 0; mt < 2; mt++)
#pragma unroll
        for (int nt = 0; nt < 4; nt++)
#pragma unroll
            for (int q = 0; q < 4; q++) C[mt][nt][q] = 0.f;

    const __nv_bfloat16* gAh = g_s1h + (size_t)b * L1 * SC1P;
    const __nv_bfloat16* gAl = g_s1l + (size_t)b * L1 * SC1P;

    for (int cblock = 0; cblock < 8; cblock++) {
        int cb = cblock << 6;
        __syncthreads();   // prev cblock's MMA reads of A done
        // ---- A halo fill: 131 rows x 64 ch, hi+lo ----
#pragma unroll
        for (int it = 0; it < 5; it++) {
            int idx = tid + it * 256;          // need 0..1047
            if (idx < 131 * 8) {
                int row = idx >> 3, g8 = idx & 7;
                int t = t0 + row;
                uint4 vh = make_uint4(0,0,0,0), vl = make_uint4(0,0,0,0);
                if (t < L1) {
                    vh = *(const uint4*)(gAh + (size_t)t * SC1P + cb + g8 * 8);
                    vl = *(const uint4*)(gAl + (size_t)t * SC1P + cb + g8 * 8);
                }
                *(uint4*)(dsm + OFF_AH + row * 144 + g8 * 16) = vh;
                *(uint4*)(dsm + OFF_AL + row * 144 + g8 * 16) = vl;
            }
        }
        for (int kk = 0; kk < 4; kk++) {
            uint32_t buf = BBUF(kk & 1);
            // ---- B fill (kk, cblock): 64 o-rows x 64 ch ----
#pragma unroll
            for (int it = 0; it < 2; it++) {
                int idx = tid + it * 256;       // 0..511
                int o = idx >> 3, g8 = idx & 7;
                *(uint4*)(dsm + buf + o * 144 + g8 * 16) =
                    *(const uint4*)(g_wbh + (size_t)(kk * 64 + o) * SC1P + cb + g8 * 8);
                *(uint4*)(dsm + buf + 9216u + o * 144 + g8 * 16) =
                    *(const uint4*)(g_wbl + (size_t)(kk * 64 + o) * SC1P + cb + g8 * 8);
            }
            __syncthreads();

#pragma unroll
            for (int ks = 0; ks < 4; ks++) {
                int koff = (ks * 16 + 2 * t4) * 2;
                uint32_t ah[2][4], al[2][4];
#pragma unroll
                for (int mt = 0; mt < 2; mt++) {
                    int rbase = (kk + warp_m * 32 + mt * 16 + g) * 144;
                    ah[mt][0] = *(const uint32_t*)(dsm + OFF_AH + rbase + koff);
                    ah[mt][1] = *(const uint32_t*)(dsm + OFF_AH + rbase + 1152 + koff);
                    ah[mt][2] = *(const uint32_t*)(dsm + OFF_AH + rbase + koff + 16);
                    ah[mt][3] = *(const uint32_t*)(dsm + OFF_AH + rbase + 1152 + koff + 16);
                    al[mt][0] = *(const uint32_t*)(dsm + OFF_AL + rbase + koff);
                    al[mt][1] = *(const uint32_t*)(dsm + OFF_AL + rbase + 1152 + koff);
                    al[mt][2] = *(const uint32_t*)(dsm + OFF_AL + rbase + koff + 16);
                    al[mt][3] = *(const uint32_t*)(dsm + OFF_AL + rbase + 1152 + koff + 16);
                }
                uint32_t bh[4][2], bl[4][2];
#pragma unroll
                for (int nt = 0; nt < 4; nt++) {
                    int nbase = (warp_n * 32 + nt * 8 + g) * 144;
                    bh[nt][0] = *(const uint32_t*)(dsm + buf + nbase + koff);
                    bh[nt][1] = *(const uint32_t*)(dsm + buf + nbase + koff + 16);
                    bl[nt][0] = *(const uint32_t*)(dsm + buf + 9216u + nbase + koff);
                    bl[nt][1] = *(const uint32_t*)(dsm + buf + 9216u + nbase + koff + 16);
                }
#pragma unroll
                for (int mt = 0; mt < 2; mt++)
#pragma unroll
                    for (int nt = 0; nt < 4; nt++) {
                        float* c = C[mt][nt];
                        mma_bf16(c[0], c[1], c[2], c[3],
                                 ah[mt][0], ah[mt][1], ah[mt][2], ah[mt][3],
                                 bh[nt][0], bh[nt][1]);
                        mma_bf16(c[0], c[1], c[2], c[3],
                                 ah[mt][0], ah[mt][1], ah[mt][2], ah[mt][3],
                                 bl[nt][0], bl[nt][1]);
                        mma_bf16(c[0], c[1], c[2], c[3],
                                 al[mt][0], al[mt][1], al[mt][2], al[mt][3],
                                 bh[nt][0], bh[nt][1]);
                    }
            }
        }
    }
    __syncthreads();

    // ---- epilogue ----
#pragma unroll
    for (int mt = 0; mt < 2; mt++)
#pragma unroll
        for (int nt = 0; nt < 4; nt++) {
            int row = warp_m * 32 + mt * 16 + g;
            int col = warp_n * 32 + nt * 8 + 2 * t4;
            *(float2*)(dsm + OFF_Z + row * 272 + col * 4) =
                make_float2(C[mt][nt][0], C[mt][nt][1]);
            *(float2*)(dsm + OFF_Z + (row + 8) * 272 + col * 4) =
                make_float2(C[mt][nt][2], C[mt][nt][3]);
        }
    float* W1t = (float*)(dsm + OFF_W1);
    float* W2s = (float*)(dsm + OFF_W2);
    float* bss = (float*)(dsm + OFF_BS);
#pragma unroll
    for (int q = 0; q < 16; q++) {
        int idx = tid + q * 256;
        W1t[(idx & 63) * 64 + (idx >> 6)] = w1[idx];
    }
#pragma unroll
    for (int q = 0; q < 4; q++) {
        int idx = tid + q * 256;
        W2s[idx] = w2[idx];
    }
    if (tid < 64) { bss[tid] = b0[tid]; bss[64 + tid] = b1[tid]; }
    if (tid < 16) bss[128 + tid] = b2[tid];
    __syncthreads();

    int row = tid >> 1, half = tid & 1;
    int o2b = half * 32;
    float z2[32];
#pragma unroll
    for (int o = 0; o < 32; o++) z2[o] = bss[64 + o2b + o];
#pragma unroll 4
    for (int c = 0; c < 64; c++) {
        float zc = fmaxf(*(const float*)(dsm + OFF_Z + row * 272 + c * 4) + bss[c], 0.f);
        const float4* wv = (const float4*)&W1t[c * 64 + o2b];
#pragma unroll
        for (int q8 = 0; q8 < 8; q8++) {
            float4 w4 = wv[q8];
            z2[q8*4+0] += zc * w4.x; z2[q8*4+1] += zc * w4.y;
            z2[q8*4+2] += zc * w4.z; z2[q8*4+3] += zc * w4.w;
        }
    }
#pragma unroll
    for (int o = 0; o < 32; o++) z2[o] = fmaxf(z2[o], 0.f);

    float p[16];
#pragma unroll
    for (int o3 = 0; o3 < 16; o3++) {
        float s = 0.f;
        const float4* wv = (const float4*)&W2s[o3 * 64 + o2b];
#pragma unroll
        for (int q8 = 0; q8 < 8; q8++) {
            float4 w4 = wv[q8];
            s += w4.x * z2[q8*4+0] + w4.y * z2[q8*4+1]
               + w4.z * z2[q8*4+2] + w4.w * z2[q8*4+3];
        }
        p[o3] = s;
    }
#pragma unroll
    for (int o3 = 0; o3 < 16; o3++)
        p[o3] += __shfl_xor_sync(0xffffffffu, p[o3], 1);

    int t = t0 + row;
    if (t < L2) {
        int ob = half * 8;
        float4 v0 = make_float4(p[ob+0] + bss[128+ob+0], p[ob+1] + bss[128+ob+1],
                                p[ob+2] + bss[128+ob+2], p[ob+3] + bss[128+ob+3]);
        float4 v1 = make_float4(p[ob+4] + bss[128+ob+4], p[ob+5] + bss[128+ob+5],
                                p[ob+6] + bss[128+ob+6], p[ob+7] + bss[128+ob+7]);
        float* dst = &g_h2[(size_t)(b * L2 + t) * H2 + ob];
        *(float4*)dst = v0;
        *(float4*)(dst + 4) = v1;
    }
}

// ============================================================
// become_constant + sig2 + linear
// ============================================================
__global__ __launch_bounds__(256) void k_sig2(
    const int* __restrict__ lengths,
    const float* __restrict__ lw, const float* __restrict__ lb,
    float* __restrict__ out)
{
    __shared__ float hs[129][16];
    __shared__ float s2s[SIGC2];
    int b = blockIdx.x, tid = threadIdx.x;
    int adj = lengths[b] - 2 * KS + 2;
    if (adj < 1) adj = 1;
    if (adj > L2) adj = L2;
    int i = tid >> 4, j = tid & 15;
    float acc = 0.f;
    for (int c0 = 0; c0 < adj; c0 += 128) {
        for (int idx = tid; idx < 129 * 16; idx += 256) {
            int r = idx >> 4, c = idx & 15;
            int row = c0 - 1 + r;
            hs[r][c] = (row >= 0 && row < L2) ? g_h2[(size_t)(b * L2 + row) * H2 + c] : 0.f;
        }
        __syncthreads();
        int tend = min(c0 + 128, adj);
        for (int t = c0; t < tend; t++) {
            int r = t - c0 + 1;
            float hpi = hs[r-1][i], hpj = hs[r-1][j];
            float dxi = hs[r][i] - hpi, dxj = hs[r][j] - hpj;
            acc += hpi * dxj + 0.5f * dxi * dxj;
        }
        __syncthreads();
    }
    s2s[16 + tid] = acc;
    if (tid < 16) s2s[tid] = g_h2[(size_t)(b * L2 + adj - 1) * H2 + tid];
    __syncthreads();
    if (tid < OUTC) {
        float v = lb[tid];
        for (int c = 0; c < SIGC2; c++) v += lw[tid * SIGC2 + c] * s2s[c];
        out[b * OUTC + tid] = v;
    }
}

// ============================================================
extern "C" void kernel_launch(void* const* d_in, const int* in_sizes, int n_in,
                              void* d_out, int out_size) {
    const float* x      = (const float*)d_in[0];
    const int*   lens   = (const int*)  d_in[1];
    const float* a1_w0  = (const float*)d_in[2];
    const float* a1_b0  = (const float*)d_in[3];
    const float* a1_w1  = (const float*)d_in[4];
    const float* a1_b1  = (const float*)d_in[5];
    const float* a1_w2  = (const float*)d_in[6];
    const float* a1_b2  = (const float*)d_in[7];
    const float* a2_w0  = (const float*)d_in[8];
    const float* a2_b0  = (const float*)d_in[9];
    const float* a2_w1  = (const float*)d_in[10];
    const float* a2_b1  = (const float*)d_in[11];
    const float* a2_w2  = (const float*)d_in[12];
    const float* a2_b2  = (const float*)d_in[13];
    const float* lin_w  = (const float*)d_in[14];
    const float* lin_b  = (const float*)d_in[15];
    float* out = (float*)d_out;

    static bool attr_set = false;
    if (!attr_set) {
        cudaFuncSetAttribute(k_conv2_mma, cudaFuncAttributeMaxDynamicSharedMemorySize, DSMB);
        attr_set = true;
    }

    k_repack<<<512, 256>>>(a2_w0);
    k_aug1<<<dim3(8, B_), 128>>>(x, a1_w0, a1_b0, a1_w1, a1_b1, a1_w2, a1_b2);
    k_sig1_sum<<<dim3(NC1, B_), 512>>>();
    k_sig1_prefix<<<B_, 512>>>();
    k_sig1_write<<<dim3(NC1, B_), 512>>>();
    k_conv2_mma<<<dim3(8, B_), 256, DSMB>>>(a2_b0, a2_w1, a2_b1, a2_w2, a2_b2);
    k_sig2<<<B_, 256>>>(lens, lin_w, lin_b, out);
}

// round 11
// speedup vs baseline: 2.7553x; 1.0543x over previous
#include <cuda_runtime.h>
#include <cuda_bf16.h>
#include <cstdint>

#define B_    64
#define S_    1024
#define CIN   5
#define KS    4
#define H1    64
#define H2    16
#define OUTC  32
#define L1    1021
#define C1    22
#define SIGC1 506
#define SC1P  512
#define L2    1018
#define SIGC2 272
#define NC1   16
#define CH1   64

// ---- conv2 smem layout (double-buffered A and B) ----
#define ABUF(i)  ((uint32_t)(i) * 37728u)   // 131 rows x 144B, hi+lo
#define ABUF_LO  18864u
#define BBUF(i)  (75456u + (uint32_t)(i) * 18432u)  // 64 rows x 144B, hi+lo
#define BBUF_LO  9216u
#define DSMB     112320u
// epilogue overlay
#define OFF_Z   0u                 // f32 [128][68]
#define OFF_W1  36864u
#define OFF_W2  53248u
#define OFF_BS  57344u

// ---- scratch ----
__device__ float g_h[B_ * L1 * C1];
__device__ __nv_bfloat16 g_s1h[(size_t)B_ * L1 * SC1P];
__device__ __nv_bfloat16 g_s1l[(size_t)B_ * L1 * SC1P];
__device__ __nv_bfloat16 g_wbh[KS * 64 * SC1P];    // [kk][o][c]
__device__ __nv_bfloat16 g_wbl[KS * 64 * SC1P];
__device__ float g_csum[B_ * NC1 * SC1P];
__device__ float g_h2[B_ * L2 * H2];

__device__ __forceinline__ void mma_bf16(
    float& c0, float& c1, float& c2, float& c3,
    uint32_t a0, uint32_t a1, uint32_t a2, uint32_t a3,
    uint32_t b0, uint32_t b1) {
    asm volatile(
        "mma.sync.aligned.m16n8k16.row.col.f32.bf16.bf16.f32 "
        "{%0,%1,%2,%3}, {%4,%5,%6,%7}, {%8,%9}, {%0,%1,%2,%3};"
        : "+f"(c0), "+f"(c1), "+f"(c2), "+f"(c3)
        : "r"(a0), "r"(a1), "r"(a2), "r"(a3), "r"(b0), "r"(b1));
}
__device__ __forceinline__ uint32_t smem_u32(const void* p) {
    uint32_t a;
    asm("{ .reg .u64 t; cvta.to.shared.u64 t, %1; cvt.u32.u64 %0, t; }" : "=r"(a) : "l"(p));
    return a;
}
__device__ __forceinline__ void cp16(uint32_t dst, const void* src, uint32_t sz) {
    asm volatile("cp.async.cg.shared.global [%0], [%1], 16, %2;"
        :: "r"(dst), "l"(src), "r"(sz));
}
__device__ __forceinline__ void cp_commit() { asm volatile("cp.async.commit_group;"); }
__device__ __forceinline__ void cp_wait1()  { asm volatile("cp.async.wait_group 1;" ::: "memory"); }
__device__ __forceinline__ void cp_wait0()  { asm volatile("cp.async.wait_group 0;" ::: "memory"); }
__device__ __forceinline__ void ldm_x4(uint32_t& r0, uint32_t& r1, uint32_t& r2, uint32_t& r3,
                                       uint32_t a) {
    asm volatile("ldmatrix.sync.aligned.m8n8.x4.shared.b16 {%0,%1,%2,%3}, [%4];"
        : "=r"(r0), "=r"(r1), "=r"(r2), "=r"(r3) : "r"(a));
}

// ============================================================
// Repack a2_w0 (O,C,K) -> bf16 hi/lo [kk][o][512c]
// ============================================================
__global__ void k_repack(const float* __restrict__ w0) {
    int idx = blockIdx.x * blockDim.x + threadIdx.x;
    int c  = idx & 511;
    int o  = (idx >> 9) & 63;
    int kk = idx >> 15;
    float v = (c < SIGC1) ? w0[(o * SIGC1 + c) * KS + kk] : 0.f;
    __nv_bfloat16 hi = __float2bfloat16(v);
    __nv_bfloat16 lo = __float2bfloat16(v - __bfloat162float(hi));
    g_wbh[idx] = hi;
    g_wbl[idx] = lo;
}

// ============================================================
// Augment 1
// ============================================================
__global__ __launch_bounds__(128) void k_aug1(
    const float* __restrict__ x,
    const float* __restrict__ w0, const float* __restrict__ b0,
    const float* __restrict__ w1, const float* __restrict__ b1,
    const float* __restrict__ w2, const float* __restrict__ b2)
{
    __shared__ float w0s[H1*CIN*KS], w1s[H1*H1], w2s[H2*H1];
    __shared__ float b0s[H1], b1s[H1], b2s[H2];
    int tid = threadIdx.x;
    for (int i = tid; i < H1*CIN*KS; i += 128) w0s[i] = w0[i];
    for (int i = tid; i < H1*H1;     i += 128) w1s[i] = w1[i];
    for (int i = tid; i < H2*H1;     i += 128) w2s[i] = w2[i];
    if (tid < H1) { b0s[tid] = b0[tid]; b1s[tid] = b1[tid]; }
    if (tid < H2) b2s[tid] = b2[tid];
    __syncthreads();

    int b = blockIdx.y;
    int t = blockIdx.x * 128 + tid;
    if (t >= L1) return;

    float xr[KS][CIN];
#pragma unroll
    for (int k = 0; k < KS; k++)
#pragma unroll
        for (int c = 0; c < CIN; c++)
            xr[k][c] = x[((size_t)(b * S_) + t + k) * CIN + c];

    float z1[H1];
#pragma unroll
    for (int o = 0; o < H1; o++) {
        float s = b0s[o];
#pragma unroll
        for (int c = 0; c < CIN; c++)
#pragma unroll
            for (int k = 0; k < KS; k++)
                s += w0s[(o*CIN + c)*KS + k] * xr[k][c];
        z1[o] = fmaxf(s, 0.f);
    }
    float z3[H2];
#pragma unroll
    for (int o = 0; o < H2; o++) z3[o] = b2s[o];
    for (int o2 = 0; o2 < H1; o2++) {
        float s = b1s[o2];
#pragma unroll
        for (int c = 0; c < H1; c++) s += w1s[o2*H1 + c] * z1[c];
        s = fmaxf(s, 0.f);
#pragma unroll
        for (int o = 0; o < H2; o++) z3[o] += w2s[o*H1 + o2] * s;
    }
    float* hrow = &g_h[(size_t)(b * L1 + t) * C1];
#pragma unroll
    for (int c = 0; c < CIN; c++) hrow[c] = xr[KS-1][c];
    hrow[CIN] = (float)t * (1.0f / (float)(L1 - 1));
#pragma unroll
    for (int o = 0; o < H2; o++) hrow[CIN + 1 + o] = z3[o];
}

// ============================================================
// Sig1 passes
// ============================================================
__global__ __launch_bounds__(512) void k_sig1_sum() {
    __shared__ float hs[CH1 + 1][C1];
    int b = blockIdx.y, nc = blockIdx.x, tid = threadIdx.x;
    int c0 = nc * CH1;
    for (int idx = tid; idx < (CH1 + 1) * C1; idx += 512) {
        int r = idx / C1, c = idx - r * C1;
        int row = c0 - 1 + r;
        hs[r][c] = (row >= 0 && row < L1) ? g_h[(size_t)(b * L1 + row) * C1 + c] : 0.f;
    }
    __syncthreads();
    if (tid >= C1 * C1) return;
    int i = tid / C1, j = tid - i * C1;
    float acc = 0.f;
    int tend = min(c0 + CH1, L1);
    for (int t = c0; t < tend; t++) {
        int r = t - c0 + 1;
        float hpi = hs[r-1][i], hpj = hs[r-1][j];
        float dxi = hs[r][i] - hpi, dxj = hs[r][j] - hpj;
        acc += hpi * dxj + 0.5f * dxi * dxj;
    }
    g_csum[(b * NC1 + nc) * SC1P + tid] = acc;
}

__global__ void k_sig1_prefix() {
    int b = blockIdx.x, tid = threadIdx.x;
    if (tid >= C1 * C1) return;
    float run = 0.f;
    for (int nc = 0; nc < NC1; nc++) {
        int idx = (b * NC1 + nc) * SC1P + tid;
        float v = g_csum[idx];
        g_csum[idx] = run;
        run += v;
    }
}

__device__ __forceinline__ void store_hl(size_t base, int ch, float v) {
    __nv_bfloat16 hi = __float2bfloat16(v);
    __nv_bfloat16 lo = __float2bfloat16(v - __bfloat162float(hi));
    g_s1h[base + ch] = hi;
    g_s1l[base + ch] = lo;
}

__global__ __launch_bounds__(512) void k_sig1_write() {
    __shared__ float hs[CH1 + 1][C1];
    int b = blockIdx.y, nc = blockIdx.x, tid = threadIdx.x;
    int c0 = nc * CH1;
    for (int idx = tid; idx < (CH1 + 1) * C1; idx += 512) {
        int r = idx / C1, c = idx - r * C1;
        int row = c0 - 1 + r;
        hs[r][c] = (row >= 0 && row < L1) ? g_h[(size_t)(b * L1 + row) * C1 + c] : 0.f;
    }
    __syncthreads();
    int tend = min(c0 + CH1, L1);
    if (tid < C1 * C1) {
        int i = tid / C1, j = tid - i * C1;
        float acc = g_csum[(b * NC1 + nc) * SC1P + tid];
        for (int t = c0; t < tend; t++) {
            int r = t - c0 + 1;
            float hpi = hs[r-1][i], hpj = hs[r-1][j];
            float dxi = hs[r][i] - hpi, dxj = hs[r][j] - hpj;
            acc += hpi * dxj + 0.5f * dxi * dxj;
            store_hl((size_t)(b * L1 + t) * SC1P, C1 + tid, acc);
        }
    } else {
        int c = tid - C1 * C1;
        int ch = (c < C1) ? c : (C1 * C1 + c);
        for (int t = c0; t < tend; t++) {
            int r = t - c0 + 1;
            float v = (c < C1) ? hs[r][c] : 0.f;
            store_hl((size_t)(b * L1 + t) * SC1P, ch, v);
        }
    }
}

// ============================================================
// Conv stack 2: split-bf16 HMMA, cp.async pipelined A/B double
// buffers, ldmatrix fragment loads, fused epilogue
// ============================================================
__global__ __launch_bounds__(256, 2) void k_conv2_mma(
    const float* __restrict__ b0,
    const float* __restrict__ w1, const float* __restrict__ b1,
    const float* __restrict__ w2, const float* __restrict__ b2)
{
    extern __shared__ __align__(16) char dsm[];
    uint32_t sb = smem_u32(dsm);
    int tid = threadIdx.x;
    int lane = tid & 31, wid = tid >> 5;
    int warp_m = wid & 3, warp_n = wid >> 2;
    int b = blockIdx.y, t0 = blockIdx.x * 128;
    int g = lane >> 2, t4 = lane & 3;

    float C[2][4][4];
#pragma unroll
    for (int mt = 0; mt < 2; mt++)
#pragma unroll
        for (int nt = 0; nt < 4; nt++)
#pragma unroll
            for (int q = 0; q < 4; q++) C[mt][nt][q] = 0.f;

    const __nv_bfloat16* gAh = g_s1h + (size_t)b * L1 * SC1P;
    const __nv_bfloat16* gAl = g_s1l + (size_t)b * L1 * SC1P;

    // per-lane ldmatrix offsets
    uint32_t aoff = (uint32_t)((lane & 15) * 144 + (lane >> 4) * 16);
    int q = lane >> 3, rr = lane & 7;
    uint32_t boff = (uint32_t)((((q >> 1) * 8) + rr) * 144 + (q & 1) * 16);

#define ISSUE_A(cb_, abuf_) do {                                            \
        int cbb_ = (cb_) << 6;                                              \
        _Pragma("unroll")                                                   \
        for (int it = 0; it < 5; it++) {                                    \
            int idx_ = tid + it * 256;                                      \
            if (idx_ < 1048) {                                              \
                int row_ = idx_ >> 3, g8_ = idx_ & 7;                       \
                int t_ = t0 + row_;                                         \
                uint32_t sz_ = (t_ < L1) ? 16u : 0u;                        \
                int tc_ = (t_ < L1) ? t_ : (L1 - 1);                        \
                uint32_t d_ = sb + (abuf_) + (uint32_t)(row_ * 144 + g8_ * 16); \
                cp16(d_, gAh + (size_t)tc_ * SC1P + cbb_ + g8_ * 8, sz_);   \
                cp16(d_ + ABUF_LO, gAl + (size_t)tc_ * SC1P + cbb_ + g8_ * 8, sz_); \
            }                                                               \
        }                                                                   \
    } while (0)

#define ISSUE_B(ph_, bbuf_) do {                                            \
        int cb_ = (ph_) >> 2, kk_ = (ph_) & 3;                              \
        int cbb_ = cb_ << 6;                                                \
        _Pragma("unroll")                                                   \
        for (int it = 0; it < 2; it++) {                                    \
            int idx_ = tid + it * 256;                                      \
            int o_ = idx_ >> 3, g8_ = idx_ & 7;                             \
            uint32_t d_ = sb + (bbuf_) + (uint32_t)(o_ * 144 + g8_ * 16);   \
            cp16(d_, g_wbh + (size_t)(kk_ * 64 + o_) * SC1P + cbb_ + g8_ * 8, 16u); \
            cp16(d_ + BBUF_LO, g_wbl + (size_t)(kk_ * 64 + o_) * SC1P + cbb_ + g8_ * 8, 16u); \
        }                                                                   \
    } while (0)

    ISSUE_A(0, ABUF(0));
    ISSUE_B(0, BBUF(0));
    cp_commit();

    for (int p = 0; p < 32; p++) {
        int cb = p >> 2, kk = p & 3;
        if (p < 31) {
            int pn = p + 1;
            if ((pn & 3) == 0) ISSUE_A(pn >> 2, ABUF((pn >> 2) & 1));
            ISSUE_B(pn, BBUF(pn & 1));
            cp_commit();
            cp_wait1();
        } else {
            cp_wait0();
        }
        __syncthreads();

        uint32_t Ah = sb + ABUF(cb & 1) + (uint32_t)((kk + warp_m * 32) * 144) + aoff;
        uint32_t Bb = sb + BBUF(p & 1) + (uint32_t)(warp_n * 32 * 144) + boff;
#pragma unroll
        for (int ks = 0; ks < 4; ks++) {
            uint32_t ko = (uint32_t)(ks * 32);
            uint32_t ah[2][4], al[2][4], bh[4][2], bl[4][2];
#pragma unroll
            for (int mt = 0; mt < 2; mt++) {
                ldm_x4(ah[mt][0], ah[mt][1], ah[mt][2], ah[mt][3],
                       Ah + (uint32_t)(mt * 16 * 144) + ko);
                ldm_x4(al[mt][0], al[mt][1], al[mt][2], al[mt][3],
                       Ah + ABUF_LO + (uint32_t)(mt * 16 * 144) + ko);
            }
#pragma unroll
            for (int j = 0; j < 2; j++) {
                ldm_x4(bh[2*j][0], bh[2*j][1], bh[2*j+1][0], bh[2*j+1][1],
                       Bb + (uint32_t)(j * 16 * 144) + ko);
                ldm_x4(bl[2*j][0], bl[2*j][1], bl[2*j+1][0], bl[2*j+1][1],
                       Bb + BBUF_LO + (uint32_t)(j * 16 * 144) + ko);
            }
#pragma unroll
            for (int mt = 0; mt < 2; mt++)
#pragma unroll
                for (int nt = 0; nt < 4; nt++) {
                    float* c = C[mt][nt];
                    mma_bf16(c[0], c[1], c[2], c[3],
                             ah[mt][0], ah[mt][1], ah[mt][2], ah[mt][3],
                             bh[nt][0], bh[nt][1]);
                    mma_bf16(c[0], c[1], c[2], c[3],
                             ah[mt][0], ah[mt][1], ah[mt][2], ah[mt][3],
                             bl[nt][0], bl[nt][1]);
                    mma_bf16(c[0], c[1], c[2], c[3],
                             al[mt][0], al[mt][1], al[mt][2], al[mt][3],
                             bh[nt][0], bh[nt][1]);
                }
        }
        __syncthreads();
    }

    // ---- epilogue ----
#pragma unroll
    for (int mt = 0; mt < 2; mt++)
#pragma unroll
        for (int nt = 0; nt < 4; nt++) {
            int row = warp_m * 32 + mt * 16 + g;
            int col = warp_n * 32 + nt * 8 + 2 * t4;
            *(float2*)(dsm + OFF_Z + row * 272 + col * 4) =
                make_float2(C[mt][nt][0], C[mt][nt][1]);
            *(float2*)(dsm + OFF_Z + (row + 8) * 272 + col * 4) =
                make_float2(C[mt][nt][2], C[mt][nt][3]);
        }
    float* W1t = (float*)(dsm + OFF_W1);
    float* W2s = (float*)(dsm + OFF_W2);
    float* bss = (float*)(dsm + OFF_BS);
#pragma unroll
    for (int qq = 0; qq < 16; qq++) {
        int idx = tid + qq * 256;
        W1t[(idx & 63) * 64 + (idx >> 6)] = w1[idx];
    }
#pragma unroll
    for (int qq = 0; qq < 4; qq++) {
        int idx = tid + qq * 256;
        W2s[idx] = w2[idx];
    }
    if (tid < 64) { bss[tid] = b0[tid]; bss[64 + tid] = b1[tid]; }
    if (tid < 16) bss[128 + tid] = b2[tid];
    __syncthreads();

    int row = tid >> 1, half = tid & 1;
    int o2b = half * 32;
    float z2[32];
#pragma unroll
    for (int o = 0; o < 32; o++) z2[o] = bss[64 + o2b + o];
#pragma unroll 4
    for (int c = 0; c < 64; c++) {
        float zc = fmaxf(*(const float*)(dsm + OFF_Z + row * 272 + c * 4) + bss[c], 0.f);
        const float4* wv = (const float4*)&W1t[c * 64 + o2b];
#pragma unroll
        for (int q8 = 0; q8 < 8; q8++) {
            float4 w4 = wv[q8];
            z2[q8*4+0] += zc * w4.x; z2[q8*4+1] += zc * w4.y;
            z2[q8*4+2] += zc * w4.z; z2[q8*4+3] += zc * w4.w;
        }
    }
#pragma unroll
    for (int o = 0; o < 32; o++) z2[o] = fmaxf(z2[o], 0.f);

    float p[16];
#pragma unroll
    for (int o3 = 0; o3 < 16; o3++) {
        float s = 0.f;
        const float4* wv = (const float4*)&W2s[o3 * 64 + o2b];
#pragma unroll
        for (int q8 = 0; q8 < 8; q8++) {
            float4 w4 = wv[q8];
            s += w4.x * z2[q8*4+0] + w4.y * z2[q8*4+1]
               + w4.z * z2[q8*4+2] + w4.w * z2[q8*4+3];
        }
        p[o3] = s;
    }
#pragma unroll
    for (int o3 = 0; o3 < 16; o3++)
        p[o3] += __shfl_xor_sync(0xffffffffu, p[o3], 1);

    int t = t0 + row;
    if (t < L2) {
        int ob = half * 8;
        float4 v0 = make_float4(p[ob+0] + bss[128+ob+0], p[ob+1] + bss[128+ob+1],
                                p[ob+2] + bss[128+ob+2], p[ob+3] + bss[128+ob+3]);
        float4 v1 = make_float4(p[ob+4] + bss[128+ob+4], p[ob+5] + bss[128+ob+5],
                                p[ob+6] + bss[128+ob+6], p[ob+7] + bss[128+ob+7]);
        float* dst = &g_h2[(size_t)(b * L2 + t) * H2 + ob];
        *(float4*)dst = v0;
        *(float4*)(dst + 4) = v1;
    }
}

// ============================================================
// become_constant + sig2 + linear
// ============================================================
__global__ __launch_bounds__(256) void k_sig2(
    const int* __restrict__ lengths,
    const float* __restrict__ lw, const float* __restrict__ lb,
    float* __restrict__ out)
{
    __shared__ float hs[129][16];
    __shared__ float s2s[SIGC2];
    int b = blockIdx.x, tid = threadIdx.x;
    int adj = lengths[b] - 2 * KS + 2;
    if (adj < 1) adj = 1;
    if (adj > L2) adj = L2;
    int i = tid >> 4, j = tid & 15;
    float acc = 0.f;
    for (int c0 = 0; c0 < adj; c0 += 128) {
        for (int idx = tid; idx < 129 * 16; idx += 256) {
            int r = idx >> 4, c = idx & 15;
            int row = c0 - 1 + r;
            hs[r][c] = (row >= 0 && row < L2) ? g_h2[(size_t)(b * L2 + row) * H2 + c] : 0.f;
        }
        __syncthreads();
        int tend = min(c0 + 128, adj);
        for (int t = c0; t < tend; t++) {
            int r = t - c0 + 1;
            float hpi = hs[r-1][i], hpj = hs[r-1][j];
            float dxi = hs[r][i] - hpi, dxj = hs[r][j] - hpj;
            acc += hpi * dxj + 0.5f * dxi * dxj;
        }
        __syncthreads();
    }
    s2s[16 + tid] = acc;
    if (tid < 16) s2s[tid] = g_h2[(size_t)(b * L2 + adj - 1) * H2 + tid];
    __syncthreads();
    if (tid < OUTC) {
        float v = lb[tid];
        for (int c = 0; c < SIGC2; c++) v += lw[tid * SIGC2 + c] * s2s[c];
        out[b * OUTC + tid] = v;
    }
}

// ============================================================
extern "C" void kernel_launch(void* const* d_in, const int* in_sizes, int n_in,
                              void* d_out, int out_size) {
    const float* x      = (const float*)d_in[0];
    const int*   lens   = (const int*)  d_in[1];
    const float* a1_w0  = (const float*)d_in[2];
    const float* a1_b0  = (const float*)d_in[3];
    const float* a1_w1  = (const float*)d_in[4];
    const float* a1_b1  = (const float*)d_in[5];
    const float* a1_w2  = (const float*)d_in[6];
    const float* a1_b2  = (const float*)d_in[7];
    const float* a2_w0  = (const float*)d_in[8];
    const float* a2_b0  = (const float*)d_in[9];
    const float* a2_w1  = (const float*)d_in[10];
    const float* a2_b1  = (const float*)d_in[11];
    const float* a2_w2  = (const float*)d_in[12];
    const float* a2_b2  = (const float*)d_in[13];
    const float* lin_w  = (const float*)d_in[14];
    const float* lin_b  = (const float*)d_in[15];
    float* out = (float*)d_out;

    static bool attr_set = false;
    if (!attr_set) {
        cudaFuncSetAttribute(k_conv2_mma, cudaFuncAttributeMaxDynamicSharedMemorySize, DSMB);
        attr_set = true;
    }

    k_repack<<<512, 256>>>(a2_w0);
    k_aug1<<<dim3(8, B_), 128>>>(x, a1_w0, a1_b0, a1_w1, a1_b1, a1_w2, a1_b2);
    k_sig1_sum<<<dim3(NC1, B_), 512>>>();
    k_sig1_prefix<<<B_, 512>>>();
    k_sig1_write<<<dim3(NC1, B_), 512>>>();
    k_conv2_mma<<<dim3(8, B_), 256, DSMB>>>(a2_b0, a2_w1, a2_b1, a2_w2, a2_b2);
    k_sig2<<<B_, 256>>>(lens, lin_w, lin_b, out);
}